// round 2
// baseline (speedup 1.0000x reference)
#include <cuda_runtime.h>
#include <cuda_bf16.h>
#include <math.h>

// Problem constants
#define Bb 2
#define Tt 4096
#define Cc 1024
#define NH 16
#define HS 64
#define BD 16
#define DELTA 32

#define TCHUNK 64
#define NROWS (TCHUNK + DELTA - 1)   // 95

// Scratch (allocation-free rule: __device__ globals)
__device__ float g_disp[Bb * Tt * NH * BD];    // (b*T+t, n*16+d)   8MB
__device__ float g_val [Bb * Tt * Cc];         // (b*T+t, n*64+h)  32MB
__device__ float g_attn[Bb * Tt * Cc];         // pre-cproj        32MB
__device__ float g_pf  [DELTA * BD];           // pos_feat 32x16

// ---------------------------------------------------------------------------
// Classic 128x128x8 fp32 SGEMM, 256 threads, 8x8 register tile.
// A:(M,K) row-major, B:(K,N) row-major, C:(M,N). M%128==0, N%128==0, K%8==0.
// ---------------------------------------------------------------------------
__global__ __launch_bounds__(256) void sgemm128(const float* __restrict__ A,
                                                const float* __restrict__ B,
                                                float* __restrict__ C,
                                                int M, int N, int K) {
    __shared__ float As[8][128];
    __shared__ float Bs[8][128];
    int tid = threadIdx.x;
    int rowC = blockIdx.y * 128;
    int colC = blockIdx.x * 128;

    int arow = tid >> 1;            // 0..127
    int acol = (tid & 1) * 4;       // 0 or 4
    int brow = tid >> 5;            // 0..7
    int bcol = (tid & 31) * 4;      // 0..124

    int tx = tid & 15;              // 0..15
    int ty = tid >> 4;              // 0..15

    float acc[8][8];
#pragma unroll
    for (int i = 0; i < 8; i++)
#pragma unroll
        for (int j = 0; j < 8; j++) acc[i][j] = 0.f;

    const float* Aptr = A + (size_t)(rowC + arow) * K + acol;
    const float* Bptr = B + (size_t)brow * N + colC + bcol;

    for (int k0 = 0; k0 < K; k0 += 8) {
        float4 av = *(const float4*)Aptr;
        As[acol + 0][arow] = av.x;
        As[acol + 1][arow] = av.y;
        As[acol + 2][arow] = av.z;
        As[acol + 3][arow] = av.w;
        float4 bv = *(const float4*)Bptr;
        *(float4*)&Bs[brow][bcol] = bv;
        __syncthreads();
#pragma unroll
        for (int k = 0; k < 8; k++) {
            float ar[8], br[8];
            float4 a0 = *(const float4*)&As[k][ty * 8];
            float4 a1 = *(const float4*)&As[k][ty * 8 + 4];
            ar[0]=a0.x; ar[1]=a0.y; ar[2]=a0.z; ar[3]=a0.w;
            ar[4]=a1.x; ar[5]=a1.y; ar[6]=a1.z; ar[7]=a1.w;
            float4 b0 = *(const float4*)&Bs[k][tx * 8];
            float4 b1 = *(const float4*)&Bs[k][tx * 8 + 4];
            br[0]=b0.x; br[1]=b0.y; br[2]=b0.z; br[3]=b0.w;
            br[4]=b1.x; br[5]=b1.y; br[6]=b1.z; br[7]=b1.w;
#pragma unroll
            for (int i = 0; i < 8; i++)
#pragma unroll
                for (int j = 0; j < 8; j++)
                    acc[i][j] += ar[i] * br[j];
        }
        __syncthreads();
        Aptr += 8;
        Bptr += (size_t)8 * N;
    }

#pragma unroll
    for (int i = 0; i < 8; i++) {
        float* crow = C + (size_t)(rowC + ty * 8 + i) * N + colC + tx * 8;
        *(float4*)(crow)     = make_float4(acc[i][0], acc[i][1], acc[i][2], acc[i][3]);
        *(float4*)(crow + 4) = make_float4(acc[i][4], acc[i][5], acc[i][6], acc[i][7]);
    }
}

// ---------------------------------------------------------------------------
// pos_feat = rel_pos_emb(32x16) @ W_pos(16x16)
// ---------------------------------------------------------------------------
__global__ void posfeat_kernel(const float* __restrict__ rel,
                               const float* __restrict__ Wp) {
    int t = threadIdx.x;          // 0..511
    int r = t >> 4, c = t & 15;
    float acc = 0.f;
#pragma unroll
    for (int k = 0; k < 16; k++) acc += rel[r * 16 + k] * Wp[k * 16 + c];
    g_pf[r * 16 + c] = acc;
}

__device__ __forceinline__ float gelu_exact(float v) {
    return 0.5f * v * (1.0f + erff(v * 0.70710678118654752f));
}

// ---------------------------------------------------------------------------
// Windowed attention: one block = (b, head n, 64 t's). 256 threads = 8 warps,
// each warp does 8 t's; lane = window position j.
// ---------------------------------------------------------------------------
__global__ __launch_bounds__(256) void attn_kernel(const float* __restrict__ W_sf,
                                                   const float* __restrict__ b_sf,
                                                   const float* __restrict__ w_bond,
                                                   const float* __restrict__ w_dmg,
                                                   const float* __restrict__ pb_dmg) {
    __shared__ float sm_val [NROWS * 64];       // val rows for window
    __shared__ float sm_disp[NROWS * 17];       // disp rows, padded stride 17
    __shared__ float sm_Wsf[16 * 32];
    __shared__ float sm_pf [32 * 17];           // pos_feat, padded stride 17
    __shared__ float sm_bsf[32];
    __shared__ float sm_wb[16], sm_wd[16];

    int tid  = threadIdx.x;
    int t0   = blockIdx.x * TCHUNK;
    int n    = blockIdx.y;
    int b    = blockIdx.z;

    const float* valp  = g_val  + (size_t)b * Tt * Cc;
    const float* dispp = g_disp + (size_t)b * Tt * (NH * BD);
    float* outp        = g_attn + (size_t)b * Tt * Cc;

    // load tiles
    for (int idx = tid; idx < NROWS * 64; idx += 256) {
        int r = idx >> 6, h = idx & 63;
        int g = t0 - (DELTA - 1) + r;
        sm_val[r * 64 + h] = (g >= 0) ? valp[(size_t)g * Cc + n * HS + h] : 0.f;
    }
    for (int idx = tid; idx < NROWS * 16; idx += 256) {
        int r = idx >> 4, d = idx & 15;
        int g = t0 - (DELTA - 1) + r;
        sm_disp[r * 17 + d] = (g >= 0) ? dispp[(size_t)g * (NH * BD) + n * BD + d] : 0.f;
    }
    for (int idx = tid; idx < 512; idx += 256) sm_Wsf[idx] = W_sf[idx];
    for (int idx = tid; idx < 512; idx += 256) {
        int r = idx >> 4, c = idx & 15;
        sm_pf[r * 17 + c] = g_pf[idx];
    }
    if (tid < 32) sm_bsf[tid] = b_sf[tid];
    if (tid < 16) { sm_wb[tid] = w_bond[tid]; sm_wd[tid] = w_dmg[tid]; }
    __syncthreads();

    const float bdmg = pb_dmg[0];
    int warp = tid >> 5;
    int lane = tid & 31;

#pragma unroll 1
    for (int i = 0; i < 8; i++) {
        int tl = warp * 8 + i;         // local t, 0..63
        int t  = t0 + tl;

        // strain for window pos j=lane: disp[t+j-31] - disp[t]
        float s[16];
        const float* selfrow = &sm_disp[(tl + DELTA - 1) * 17];
        const float* wrow    = &sm_disp[(tl + lane) * 17];
#pragma unroll
        for (int d = 0; d < 16; d++) s[d] = wrow[d] - selfrow[d];

        float bond = 0.f, dacc = 0.f;
#pragma unroll
        for (int o = 0; o < 32; o++) {
            float f = sm_bsf[o];
#pragma unroll
            for (int d = 0; d < 16; d++) f += s[d] * sm_Wsf[d * 32 + o];
            if (o < 16) {
                bond += gelu_exact(f + sm_pf[lane * 17 + o]) * sm_wb[o];
            } else {
                dacc += gelu_exact(f) * sm_wd[o - 16];
            }
        }
        float dmg   = 1.f / (1.f + expf(-(dacc + bdmg)));
        float score = bond - 10.f * dmg;
        if (t + lane < DELTA - 1) score = -1e30f;   // causal window mask

        // warp softmax over j
        float m = score;
#pragma unroll
        for (int off = 16; off > 0; off >>= 1)
            m = fmaxf(m, __shfl_xor_sync(0xFFFFFFFFu, m, off));
        float e = expf(score - m);
        float ssum = e;
#pragma unroll
        for (int off = 16; off > 0; off >>= 1)
            ssum += __shfl_xor_sync(0xFFFFFFFFu, ssum, off);
        float w = e / ssum;

        // out[h] = sum_j w_j * val[t+j-31][h]; lane handles h=lane, lane+32
        float acc0 = 0.f, acc1 = 0.f;
#pragma unroll
        for (int j2 = 0; j2 < 32; j2++) {
            float wj = __shfl_sync(0xFFFFFFFFu, w, j2);
            const float* vrow = &sm_val[(tl + j2) * 64];
            acc0 += wj * vrow[lane];
            acc1 += wj * vrow[lane + 32];
        }
        float* orow = outp + (size_t)t * Cc + n * HS;
        orow[lane]      = acc0;
        orow[lane + 32] = acc1;
    }
}

// ---------------------------------------------------------------------------
extern "C" void kernel_launch(void* const* d_in, const int* in_sizes, int n_in,
                              void* d_out, int out_size) {
    const float* x       = (const float*)d_in[0];   // (B,T,C)
    const float* W_disp  = (const float*)d_in[1];   // (C, 256)
    const float* W_val   = (const float*)d_in[2];   // (C, C)
    const float* rel_pos = (const float*)d_in[3];   // (32,16)
    const float* W_pos   = (const float*)d_in[4];   // (16,16)
    const float* W_sf    = (const float*)d_in[5];   // (16,32)
    const float* b_sf    = (const float*)d_in[6];   // (32,)
    const float* w_bond  = (const float*)d_in[7];   // (16,)
    const float* w_dmg   = (const float*)d_in[8];   // (16,)
    const float* b_dmg   = (const float*)d_in[9];   // scalar
    const float* W_cproj = (const float*)d_in[10];  // (C, C)
    float* out = (float*)d_out;

    float *disp_p, *val_p, *attn_p;
    cudaGetSymbolAddress((void**)&disp_p, g_disp);
    cudaGetSymbolAddress((void**)&val_p,  g_val);
    cudaGetSymbolAddress((void**)&attn_p, g_attn);

    const int M = Bb * Tt;   // 8192

    // disp = x @ W_disp : (8192,1024)x(1024,256)
    sgemm128<<<dim3(256 / 128, M / 128), 256>>>(x, W_disp, disp_p, M, NH * BD, Cc);
    // val = x @ W_val : (8192,1024)x(1024,1024)
    sgemm128<<<dim3(Cc / 128, M / 128), 256>>>(x, W_val, val_p, M, Cc, Cc);
    // pos_feat
    posfeat_kernel<<<1, 512>>>(rel_pos, W_pos);
    // attention
    attn_kernel<<<dim3(Tt / TCHUNK, NH, Bb), 256>>>(W_sf, b_sf, w_bond, w_dmg, b_dmg);
    // out = attn @ W_cproj
    sgemm128<<<dim3(Cc / 128, M / 128), 256>>>(attn_p, W_cproj, out, M, Cc, Cc);
}

// round 4
// speedup vs baseline: 2.1222x; 2.1222x over previous
#include <cuda_runtime.h>
#include <cuda_bf16.h>
#include <math.h>
#include <stdint.h>

// Problem constants
#define Bb 2
#define Tt 4096
#define Cc 1024
#define NH 16
#define HS 64
#define BD 16
#define DELTA 32

#define TCHUNK 64
#define NROWS (TCHUNK + DELTA - 1)   // 95

#define MTOT (Bb * Tt)               // 8192

// Detect arch-specific ('a') compilation pass: tcgen05 only legal there.
#if defined(__CUDA_ARCH_FEAT_SM103_ALL) || \
    (defined(__CUDA_ARCH_SPECIFIC__) && defined(__CUDA_ARCH__) && (__CUDA_ARCH__ == 1030))
#define USE_TCGEN05 1
#else
#define USE_TCGEN05 0
#endif

// ---------------------------------------------------------------------------
// Scratch (__device__ globals; no allocations allowed)
// ---------------------------------------------------------------------------
__device__ float g_disp[MTOT * NH * BD];
__device__ float g_val [MTOT * Cc];
__device__ float g_attn[MTOT * Cc];
__device__ float g_pf  [DELTA * BD];

__device__ __nv_bfloat16 g_xhi[MTOT * Cc];
__device__ __nv_bfloat16 g_xlo[MTOT * Cc];
__device__ __nv_bfloat16 g_ahi[MTOT * Cc];
__device__ __nv_bfloat16 g_alo[MTOT * Cc];
__device__ __nv_bfloat16 g_wdh[256 * Cc];
__device__ __nv_bfloat16 g_wdl[256 * Cc];
__device__ __nv_bfloat16 g_wvh[Cc * Cc];
__device__ __nv_bfloat16 g_wvl[Cc * Cc];
__device__ __nv_bfloat16 g_wch[Cc * Cc];
__device__ __nv_bfloat16 g_wcl[Cc * Cc];

// ---------------------------------------------------------------------------
// Generic helpers
// ---------------------------------------------------------------------------
__device__ __forceinline__ uint32_t smem_u32(const void* p) {
    uint32_t a;
    asm("{ .reg .u64 t; cvta.to.shared.u64 t, %1; cvt.u32.u64 %0, t; }"
        : "=r"(a) : "l"(p));
    return a;
}

// --- HMMA fallback primitives (legal on plain sm_103) ---
__device__ __forceinline__ void cp_async16(uint32_t s, const void* g) {
    asm volatile("cp.async.cg.shared.global [%0], [%1], 16;" :: "r"(s), "l"(g) : "memory");
}
#define CP_COMMIT() asm volatile("cp.async.commit_group;" ::: "memory")
template <int N> __device__ __forceinline__ void cp_wait() {
    asm volatile("cp.async.wait_group %0;" :: "n"(N) : "memory");
}
__device__ __forceinline__ void ldsm_x4(uint32_t addr, uint32_t* r) {
    asm volatile("ldmatrix.sync.aligned.m8n8.x4.shared.b16 {%0,%1,%2,%3}, [%4];"
                 : "=r"(r[0]), "=r"(r[1]), "=r"(r[2]), "=r"(r[3]) : "r"(addr));
}
__device__ __forceinline__ void ldsm_x2(uint32_t addr, uint32_t* r) {
    asm volatile("ldmatrix.sync.aligned.m8n8.x2.shared.b16 {%0,%1}, [%2];"
                 : "=r"(r[0]), "=r"(r[1]) : "r"(addr));
}
__device__ __forceinline__ void mma16816(float* d, const uint32_t* a, const uint32_t* b) {
    asm volatile(
        "mma.sync.aligned.m16n8k16.row.col.f32.bf16.bf16.f32 "
        "{%0,%1,%2,%3}, {%4,%5,%6,%7}, {%8,%9}, {%0,%1,%2,%3};"
        : "+f"(d[0]), "+f"(d[1]), "+f"(d[2]), "+f"(d[3])
        : "r"(a[0]), "r"(a[1]), "r"(a[2]), "r"(a[3]), "r"(b[0]), "r"(b[1]));
}

#if USE_TCGEN05
// --- tcgen05 primitives (arch-specific pass only) ---
__device__ __forceinline__ uint32_t elect_one() {
    uint32_t p;
    asm volatile("{\n\t.reg .pred p;\n\telect.sync _|p, 0xFFFFFFFF;\n\t"
                 "selp.b32 %0, 1, 0, p;\n\t}" : "=r"(p));
    return p;
}
#define MBAR_INIT(addr, cnt) \
    asm volatile("mbarrier.init.shared.b64 [%0], %1;" :: "r"(addr), "r"(cnt) : "memory")
#define MBAR_INVAL(addr) \
    asm volatile("mbarrier.inval.shared.b64 [%0];" :: "r"(addr) : "memory")
#define MBAR_WAIT_PARITY(mbar_addr, phase_parity) do {                         \
    uint32_t _mbar = (uint32_t)(mbar_addr);                                    \
    uint32_t _par  = (uint32_t)(phase_parity);                                 \
    uint32_t _done;                                                            \
    asm volatile("{\n\t.reg .pred p;\n\t"                                      \
        "mbarrier.try_wait.parity.acquire.cta.shared::cta.b64 p, [%1], %2;\n\t"\
        "selp.b32 %0, 1, 0, p;\n\t}"                                           \
        : "=r"(_done) : "r"(_mbar), "r"(_par) : "memory");                     \
    if (!_done) {                                                              \
        asm volatile("{\n\t.reg .pred P1;\n\t"                                 \
            "WAIT_LOOP_%=:\n\t"                                                \
            "mbarrier.try_wait.parity.acquire.cta.shared::cta.b64 P1, [%0], %1, 0x989680;\n\t" \
            "@P1 bra.uni WAIT_DONE_%=;\n\t"                                    \
            "bra.uni WAIT_LOOP_%=;\n\t"                                        \
            "WAIT_DONE_%=:\n\t}"                                               \
            :: "r"(_mbar), "r"(_par) : "memory");                              \
    }                                                                          \
} while (0)

#define TC_ALLOC(smem_res, ncols) \
    asm volatile("tcgen05.alloc.cta_group::1.sync.aligned.shared::cta.b32 [%0], %1;" \
                 :: "r"((uint32_t)(smem_res)), "r"((uint32_t)(ncols)) : "memory")
#define TC_DEALLOC(tmem, ncols) \
    asm volatile("tcgen05.dealloc.cta_group::1.sync.aligned.b32 %0, %1;" \
                 :: "r"(tmem), "r"((uint32_t)(ncols)))
#define TC_RELINQ() \
    asm volatile("tcgen05.relinquish_alloc_permit.cta_group::1.sync.aligned;")
#define TC_COMMIT(mbar) \
    asm volatile("tcgen05.commit.cta_group::1.mbarrier::arrive::one.shared::cluster.b64 [%0];" \
                 :: "r"((uint32_t)(mbar)) : "memory")
#define TC_FENCE_AFTER() \
    asm volatile("tcgen05.fence::after_thread_sync;" ::: "memory")
#define FENCE_ASYNC_SHARED() \
    asm volatile("fence.proxy.async.shared::cta;" ::: "memory")
#define TC_WAIT_LD() \
    asm volatile("tcgen05.wait::ld.sync.aligned;" ::: "memory")

#define TC_LD_X32(r, tmem_addr)                                                \
    asm volatile(                                                              \
        "tcgen05.ld.sync.aligned.32x32b.x32.b32 "                              \
        "{%0, %1, %2, %3, %4, %5, %6, %7, "                                    \
        " %8, %9, %10, %11, %12, %13, %14, %15, "                              \
        " %16, %17, %18, %19, %20, %21, %22, %23, "                            \
        " %24, %25, %26, %27, %28, %29, %30, %31}, [%32];"                     \
        : "=r"((r)[0]),  "=r"((r)[1]),  "=r"((r)[2]),  "=r"((r)[3]),           \
          "=r"((r)[4]),  "=r"((r)[5]),  "=r"((r)[6]),  "=r"((r)[7]),           \
          "=r"((r)[8]),  "=r"((r)[9]),  "=r"((r)[10]), "=r"((r)[11]),          \
          "=r"((r)[12]), "=r"((r)[13]), "=r"((r)[14]), "=r"((r)[15]),          \
          "=r"((r)[16]), "=r"((r)[17]), "=r"((r)[18]), "=r"((r)[19]),          \
          "=r"((r)[20]), "=r"((r)[21]), "=r"((r)[22]), "=r"((r)[23]),          \
          "=r"((r)[24]), "=r"((r)[25]), "=r"((r)[26]), "=r"((r)[27]),          \
          "=r"((r)[28]), "=r"((r)[29]), "=r"((r)[30]), "=r"((r)[31])           \
        : "r"(tmem_addr))

__device__ __forceinline__ void mma_bf16_ss(uint32_t d, uint64_t ad, uint64_t bd,
                                            uint32_t idesc, uint32_t en) {
    asm volatile("{\n\t.reg .pred p;\n\tsetp.ne.u32 p, %5, 0;\n\t"
                 "tcgen05.mma.cta_group::1.kind::f16 [%0], %1, %2, %3, "
                 "{%4, %4, %4, %4}, p;\n\t}"
                 :: "r"(d), "l"(ad), "l"(bd), "r"(idesc), "r"(0u), "r"(en)
                 : "memory");
}
static constexpr uint64_t DESC_BASE_SW128 =
    (uint64_t(2) << 61) | (uint64_t(1) << 46) | (uint64_t(64) << 32) | (uint64_t(1) << 16);
__device__ __forceinline__ uint64_t make_desc(uint32_t addr) {
    return DESC_BASE_SW128 | ((uint64_t)(addr >> 4) & 0x3FFF);
}
// idesc: F32 acc, BF16xBF16, N=128, M=128
#define TG_IDESC 0x08200490u
#endif  // USE_TCGEN05

// ---------------------------------------------------------------------------
// Split fp32 -> (hi, lo) bf16
// ---------------------------------------------------------------------------
__global__ __launch_bounds__(256) void split4_kernel(const float* __restrict__ src,
                                                     __nv_bfloat16* __restrict__ hi,
                                                     __nv_bfloat16* __restrict__ lo,
                                                     int n) {
    int i = (blockIdx.x * 256 + threadIdx.x) * 4;
    if (i >= n) return;
    float4 v = *(const float4*)(src + i);
    __nv_bfloat16 h0 = __float2bfloat16(v.x);
    __nv_bfloat16 h1 = __float2bfloat16(v.y);
    __nv_bfloat16 h2 = __float2bfloat16(v.z);
    __nv_bfloat16 h3 = __float2bfloat16(v.w);
    __nv_bfloat16 l0 = __float2bfloat16(v.x - __bfloat162float(h0));
    __nv_bfloat16 l1 = __float2bfloat16(v.y - __bfloat162float(h1));
    __nv_bfloat16 l2 = __float2bfloat16(v.z - __bfloat162float(h2));
    __nv_bfloat16 l3 = __float2bfloat16(v.w - __bfloat162float(h3));
    __nv_bfloat162 hh0; hh0.x = h0; hh0.y = h1;
    __nv_bfloat162 hh1; hh1.x = h2; hh1.y = h3;
    __nv_bfloat162 ll0; ll0.x = l0; ll0.y = l1;
    __nv_bfloat162 ll1; ll1.x = l2; ll1.y = l3;
    *(__nv_bfloat162*)(hi + i)     = hh0;
    *(__nv_bfloat162*)(hi + i + 2) = hh1;
    *(__nv_bfloat162*)(lo + i)     = ll0;
    *(__nv_bfloat162*)(lo + i + 2) = ll1;
}

// ---------------------------------------------------------------------------
// Transpose + split: W (K,N) fp32 -> Wt hi/lo (N,K) bf16
// ---------------------------------------------------------------------------
__global__ __launch_bounds__(256) void tsplit_kernel(const float* __restrict__ W,
                                                     __nv_bfloat16* __restrict__ Th,
                                                     __nv_bfloat16* __restrict__ Tl,
                                                     int K, int N) {
    __shared__ float tile[32][33];
    int n0 = blockIdx.x * 32, k0 = blockIdx.y * 32;
    int tx = threadIdx.x, ty0 = threadIdx.y;
    for (int ty = ty0; ty < 32; ty += 8)
        tile[ty][tx] = W[(size_t)(k0 + ty) * N + n0 + tx];
    __syncthreads();
    for (int ty = ty0; ty < 32; ty += 8) {
        float v = tile[tx][ty];
        __nv_bfloat16 h = __float2bfloat16(v);
        __nv_bfloat16 l = __float2bfloat16(v - __bfloat162float(h));
        size_t o = (size_t)(n0 + ty) * K + k0 + tx;
        Th[o] = h;
        Tl[o] = l;
    }
}

// ---------------------------------------------------------------------------
// Tensor-core split-GEMM: C(M,N) = (Ahi+Alo)(Bhi+Blo)^T, HH+HL+LH terms.
// tcgen05 on 'a' pass; mma.sync HMMA fallback otherwise.
// ---------------------------------------------------------------------------
#define TG_SMEM_BYTES 148480

__global__ __launch_bounds__(256) void tgemm_kernel(const __nv_bfloat16* __restrict__ Ahi,
                                                    const __nv_bfloat16* __restrict__ Alo,
                                                    const __nv_bfloat16* __restrict__ Bhi,
                                                    const __nv_bfloat16* __restrict__ Blo,
                                                    float* __restrict__ C,
                                                    int M, int N, int K) {
    extern __shared__ char dsm[];
    int tid = threadIdx.x;
    int rowC = blockIdx.y * 128;
    int colC = blockIdx.x * 128;

#if USE_TCGEN05
    uint32_t smb = smem_u32(dsm);
    const uint32_t mbar = smb + 8;
    int wid = tid >> 5;

    if (wid == 0) TC_ALLOC(smb + 0, 128);
    if (tid == 0) MBAR_INIT(mbar, 1);
    __syncthreads();
    uint32_t tmem;
    asm volatile("ld.shared.b32 %0, [%1];" : "=r"(tmem) : "r"(smb + 0));

    const int NCHUNK = K >> 6;

    for (int c = 0; c < NCHUNK; c++) {
        if (c >= 2) MBAR_WAIT_PARITY(mbar, (c & 1));

        const int kbase = c << 6;
        char* buf = dsm + 1024 + (c & 1) * 65536;
        {
            const __nv_bfloat16* srcs[4] = { Ahi, Alo, Bhi, Blo };
            const int bases[4] = { rowC, rowC, colC, colC };
#pragma unroll
            for (int tno = 0; tno < 4; tno++) {
                const __nv_bfloat16* s = srcs[tno];
                const int r0 = bases[tno];
                char* tb = buf + tno * 16384;
#pragma unroll
                for (int it = 0; it < 4; it++) {
                    int idx = tid + it * 256;
                    int r = idx >> 3, cc = idx & 7;
                    uint4 v = *(const uint4*)(s + (size_t)(r0 + r) * K + kbase + cc * 8);
                    uint32_t off = r * 128 + cc * 16;
                    off ^= (off >> 3) & 0x70;
                    *(uint4*)(tb + off) = v;
                }
            }
        }
        FENCE_ASYNC_SHARED();
        __syncthreads();

        if (wid == 0 && elect_one()) {
            uint32_t b0 = smb + 1024 + (c & 1) * 65536;
            uint64_t dAh = make_desc(b0);
            uint64_t dAl = make_desc(b0 + 16384);
            uint64_t dBh = make_desc(b0 + 32768);
            uint64_t dBl = make_desc(b0 + 49152);
#pragma unroll
            for (int ks = 0; ks < 4; ks++)
                mma_bf16_ss(tmem, dAh + ks * 2, dBh + ks * 2, TG_IDESC,
                            (c == 0 && ks == 0) ? 0u : 1u);
#pragma unroll
            for (int ks = 0; ks < 4; ks++)
                mma_bf16_ss(tmem, dAh + ks * 2, dBl + ks * 2, TG_IDESC, 1u);
#pragma unroll
            for (int ks = 0; ks < 4; ks++)
                mma_bf16_ss(tmem, dAl + ks * 2, dBh + ks * 2, TG_IDESC, 1u);
            TC_COMMIT(mbar);
        }
    }

    MBAR_WAIT_PARITY(mbar, ((NCHUNK - 2) & 1));
    MBAR_WAIT_PARITY(mbar, ((NCHUNK - 1) & 1));
    TC_FENCE_AFTER();

    float* stage = (float*)(dsm + 1024);
#pragma unroll 1
    for (int g = 0; g < 4; g++) {
        if (tid < 128) {
            uint32_t dr[32];
            TC_LD_X32(dr, tmem + g * 32);
            TC_WAIT_LD();
            float* st = stage + tid * 36;
#pragma unroll
            for (int cc = 0; cc < 32; cc++) st[cc] = __uint_as_float(dr[cc]);
        }
        __syncthreads();
#pragma unroll
        for (int it = 0; it < 4; it++) {
            int idx = tid + it * 256;
            int r = idx >> 3, c4 = idx & 7;
            float4 v = *(float4*)(stage + r * 36 + c4 * 4);
            *(float4*)(C + (size_t)(rowC + r) * N + colC + g * 32 + c4 * 4) = v;
        }
        __syncthreads();
    }

    if (tid == 0) MBAR_INVAL(mbar);
    __syncthreads();
    if (wid == 0) {
        TC_RELINQ();
        TC_DEALLOC(tmem, 128);
    }

#else  // ------------------- HMMA mma.sync fallback -------------------------
    const int KC = 64;
    const int TILE_B = 128 * 144;          // 128 rows x 144B (64 bf16 + 8 pad)
    uint32_t sbase = smem_u32(dsm) + 1024;
    int lane = tid & 31;
    int wid  = tid >> 5;
    int wm = wid & 1;                       // 2 warp-rows of 64
    int wn = wid >> 1;                      // 4 warp-cols of 32

    float acc[4][4][4];
#pragma unroll
    for (int mb = 0; mb < 4; mb++)
#pragma unroll
        for (int nb = 0; nb < 4; nb++)
#pragma unroll
            for (int q = 0; q < 4; q++) acc[mb][nb][q] = 0.f;

    const __nv_bfloat16* srcs[4] = { Ahi, Alo, Bhi, Blo };
    const int bases[4] = { rowC, rowC, colC, colC };

    const int NC = K / KC;

    // prologue: chunk 0
    {
        int kb = 0;
#pragma unroll
        for (int it = 0; it < 16; it++) {
            int idx = tid + it * 256;
            int tno = idx >> 10;
            int rem = idx & 1023;
            int r = rem >> 3, s = rem & 7;
            uint32_t sa = sbase + tno * TILE_B + r * 144 + s * 16;
            cp_async16(sa, srcs[tno] + (size_t)(bases[tno] + r) * K + kb + s * 8);
        }
        CP_COMMIT();
    }

#pragma unroll 1
    for (int c = 0; c < NC; c++) {
        if (c + 1 < NC) {
            int buf = (c + 1) & 1;
            int kb = (c + 1) * KC;
#pragma unroll
            for (int it = 0; it < 16; it++) {
                int idx = tid + it * 256;
                int tno = idx >> 10;
                int rem = idx & 1023;
                int r = rem >> 3, s = rem & 7;
                uint32_t sa = sbase + (buf * 4 + tno) * TILE_B + r * 144 + s * 16;
                cp_async16(sa, srcs[tno] + (size_t)(bases[tno] + r) * K + kb + s * 8);
            }
            CP_COMMIT();
            cp_wait<1>();
        } else {
            cp_wait<0>();
        }
        __syncthreads();

        uint32_t ah = sbase + (c & 1) * 4 * TILE_B;
        uint32_t al = ah + TILE_B;
        uint32_t bh = ah + 2 * TILE_B;
        uint32_t bl = ah + 3 * TILE_B;

#pragma unroll
        for (int kk = 0; kk < 4; kk++) {
            uint32_t afh[4][4], afl[4][4], bfh[4][2], bfl[4][2];
#pragma unroll
            for (int mb = 0; mb < 4; mb++) {
                uint32_t off = (uint32_t)(wm * 64 + mb * 16 + (lane & 15)) * 144
                             + (uint32_t)(lane >> 4) * 16 + kk * 32;
                ldsm_x4(ah + off, afh[mb]);
                ldsm_x4(al + off, afl[mb]);
            }
#pragma unroll
            for (int nb = 0; nb < 4; nb++) {
                uint32_t off = (uint32_t)(wn * 32 + nb * 8 + (lane & 7)) * 144
                             + (uint32_t)((lane >> 3) & 1) * 16 + kk * 32;
                ldsm_x2(bh + off, bfh[nb]);
                ldsm_x2(bl + off, bfl[nb]);
            }
#pragma unroll
            for (int mb = 0; mb < 4; mb++)
#pragma unroll
                for (int nb = 0; nb < 4; nb++) {
                    mma16816(acc[mb][nb], afh[mb], bfh[nb]);
                    mma16816(acc[mb][nb], afh[mb], bfl[nb]);
                    mma16816(acc[mb][nb], afl[mb], bfh[nb]);
                }
        }
        __syncthreads();
    }

    // epilogue: direct float2 stores
#pragma unroll
    for (int mb = 0; mb < 4; mb++)
#pragma unroll
        for (int nb = 0; nb < 4; nb++) {
            int r0 = rowC + wm * 64 + mb * 16 + (lane >> 2);
            int c0 = colC + wn * 32 + nb * 8 + (lane & 3) * 2;
            *(float2*)(C + (size_t)r0 * N + c0) =
                make_float2(acc[mb][nb][0], acc[mb][nb][1]);
            *(float2*)(C + (size_t)(r0 + 8) * N + c0) =
                make_float2(acc[mb][nb][2], acc[mb][nb][3]);
        }
#endif
}

// ---------------------------------------------------------------------------
// pos_feat = rel_pos_emb(32x16) @ W_pos(16x16)
// ---------------------------------------------------------------------------
__global__ void posfeat_kernel(const float* __restrict__ rel,
                               const float* __restrict__ Wp) {
    int t = threadIdx.x;
    int r = t >> 4, c = t & 15;
    float acc = 0.f;
#pragma unroll
    for (int k = 0; k < 16; k++) acc += rel[r * 16 + k] * Wp[k * 16 + c];
    g_pf[r * 16 + c] = acc;
}

__device__ __forceinline__ float gelu_exact(float v) {
    return 0.5f * v * (1.0f + erff(v * 0.70710678118654752f));
}

// ---------------------------------------------------------------------------
// Windowed attention (unchanged)
// ---------------------------------------------------------------------------
__global__ __launch_bounds__(256) void attn_kernel(const float* __restrict__ W_sf,
                                                   const float* __restrict__ b_sf,
                                                   const float* __restrict__ w_bond,
                                                   const float* __restrict__ w_dmg,
                                                   const float* __restrict__ pb_dmg) {
    __shared__ float sm_val [NROWS * 64];
    __shared__ float sm_disp[NROWS * 17];
    __shared__ float sm_Wsf[16 * 32];
    __shared__ float sm_pf [32 * 17];
    __shared__ float sm_bsf[32];
    __shared__ float sm_wb[16], sm_wd[16];

    int tid  = threadIdx.x;
    int t0   = blockIdx.x * TCHUNK;
    int n    = blockIdx.y;
    int b    = blockIdx.z;

    const float* valp  = g_val  + (size_t)b * Tt * Cc;
    const float* dispp = g_disp + (size_t)b * Tt * (NH * BD);
    float* outp        = g_attn + (size_t)b * Tt * Cc;

    for (int idx = tid; idx < NROWS * 64; idx += 256) {
        int r = idx >> 6, h = idx & 63;
        int g = t0 - (DELTA - 1) + r;
        sm_val[r * 64 + h] = (g >= 0) ? valp[(size_t)g * Cc + n * HS + h] : 0.f;
    }
    for (int idx = tid; idx < NROWS * 16; idx += 256) {
        int r = idx >> 4, d = idx & 15;
        int g = t0 - (DELTA - 1) + r;
        sm_disp[r * 17 + d] = (g >= 0) ? dispp[(size_t)g * (NH * BD) + n * BD + d] : 0.f;
    }
    for (int idx = tid; idx < 512; idx += 256) sm_Wsf[idx] = W_sf[idx];
    for (int idx = tid; idx < 512; idx += 256) {
        int r = idx >> 4, c = idx & 15;
        sm_pf[r * 17 + c] = g_pf[idx];
    }
    if (tid < 32) sm_bsf[tid] = b_sf[tid];
    if (tid < 16) { sm_wb[tid] = w_bond[tid]; sm_wd[tid] = w_dmg[tid]; }
    __syncthreads();

    const float bdmg = pb_dmg[0];
    int warp = tid >> 5;
    int lane = tid & 31;

#pragma unroll 1
    for (int i = 0; i < 8; i++) {
        int tl = warp * 8 + i;
        int t  = t0 + tl;

        float s[16];
        const float* selfrow = &sm_disp[(tl + DELTA - 1) * 17];
        const float* wrow    = &sm_disp[(tl + lane) * 17];
#pragma unroll
        for (int d = 0; d < 16; d++) s[d] = wrow[d] - selfrow[d];

        float bond = 0.f, dacc = 0.f;
#pragma unroll
        for (int o = 0; o < 32; o++) {
            float f = sm_bsf[o];
#pragma unroll
            for (int d = 0; d < 16; d++) f += s[d] * sm_Wsf[d * 32 + o];
            if (o < 16) {
                bond += gelu_exact(f + sm_pf[lane * 17 + o]) * sm_wb[o];
            } else {
                dacc += gelu_exact(f) * sm_wd[o - 16];
            }
        }
        float dmg   = 1.f / (1.f + expf(-(dacc + bdmg)));
        float score = bond - 10.f * dmg;
        if (t + lane < DELTA - 1) score = -1e30f;

        float m = score;
#pragma unroll
        for (int off = 16; off > 0; off >>= 1)
            m = fmaxf(m, __shfl_xor_sync(0xFFFFFFFFu, m, off));
        float e = expf(score - m);
        float ssum = e;
#pragma unroll
        for (int off = 16; off > 0; off >>= 1)
            ssum += __shfl_xor_sync(0xFFFFFFFFu, ssum, off);
        float w = e / ssum;

        float acc0 = 0.f, acc1 = 0.f;
#pragma unroll
        for (int j2 = 0; j2 < 32; j2++) {
            float wj = __shfl_sync(0xFFFFFFFFu, w, j2);
            const float* vrow = &sm_val[(tl + j2) * 64];
            acc0 += wj * vrow[lane];
            acc1 += wj * vrow[lane + 32];
        }
        float* orow = outp + (size_t)t * Cc + n * HS;
        orow[lane]      = acc0;
        orow[lane + 32] = acc1;
    }
}

// ---------------------------------------------------------------------------
extern "C" void kernel_launch(void* const* d_in, const int* in_sizes, int n_in,
                              void* d_out, int out_size) {
    const float* x       = (const float*)d_in[0];
    const float* W_disp  = (const float*)d_in[1];
    const float* W_val   = (const float*)d_in[2];
    const float* rel_pos = (const float*)d_in[3];
    const float* W_pos   = (const float*)d_in[4];
    const float* W_sf    = (const float*)d_in[5];
    const float* b_sf    = (const float*)d_in[6];
    const float* w_bond  = (const float*)d_in[7];
    const float* w_dmg   = (const float*)d_in[8];
    const float* b_dmg   = (const float*)d_in[9];
    const float* W_cproj = (const float*)d_in[10];
    float* out = (float*)d_out;

    float *disp_p, *val_p, *attn_p;
    __nv_bfloat16 *xhi, *xlo, *ahi, *alo, *wdh, *wdl, *wvh, *wvl, *wch, *wcl;
    cudaGetSymbolAddress((void**)&disp_p, g_disp);
    cudaGetSymbolAddress((void**)&val_p,  g_val);
    cudaGetSymbolAddress((void**)&attn_p, g_attn);
    cudaGetSymbolAddress((void**)&xhi, g_xhi);
    cudaGetSymbolAddress((void**)&xlo, g_xlo);
    cudaGetSymbolAddress((void**)&ahi, g_ahi);
    cudaGetSymbolAddress((void**)&alo, g_alo);
    cudaGetSymbolAddress((void**)&wdh, g_wdh);
    cudaGetSymbolAddress((void**)&wdl, g_wdl);
    cudaGetSymbolAddress((void**)&wvh, g_wvh);
    cudaGetSymbolAddress((void**)&wvl, g_wvl);
    cudaGetSymbolAddress((void**)&wch, g_wch);
    cudaGetSymbolAddress((void**)&wcl, g_wcl);

    cudaFuncSetAttribute(tgemm_kernel,
                         cudaFuncAttributeMaxDynamicSharedMemorySize, TG_SMEM_BYTES);

    const int M = MTOT;
    const int NELEM = M * Cc;

    split4_kernel<<<NELEM / 1024, 256>>>(x, xhi, xlo, NELEM);
    tsplit_kernel<<<dim3(256 / 32, Cc / 32), dim3(32, 8)>>>(W_disp, wdh, wdl, Cc, 256);
    tsplit_kernel<<<dim3(Cc / 32, Cc / 32), dim3(32, 8)>>>(W_val,  wvh, wvl, Cc, Cc);
    tsplit_kernel<<<dim3(Cc / 32, Cc / 32), dim3(32, 8)>>>(W_cproj, wch, wcl, Cc, Cc);

    tgemm_kernel<<<dim3(256 / 128, M / 128), 256, TG_SMEM_BYTES>>>(
        xhi, xlo, wdh, wdl, disp_p, M, 256, Cc);
    tgemm_kernel<<<dim3(Cc / 128, M / 128), 256, TG_SMEM_BYTES>>>(
        xhi, xlo, wvh, wvl, val_p, M, Cc, Cc);

    posfeat_kernel<<<1, 512>>>(rel_pos, W_pos);
    attn_kernel<<<dim3(Tt / TCHUNK, NH, Bb), 256>>>(W_sf, b_sf, w_bond, w_dmg, b_dmg);

    split4_kernel<<<NELEM / 1024, 256>>>(attn_p, ahi, alo, NELEM);
    tgemm_kernel<<<dim3(Cc / 128, M / 128), 256, TG_SMEM_BYTES>>>(
        ahi, alo, wch, wcl, out, M, Cc, Cc);
}

// round 6
// speedup vs baseline: 2.4266x; 1.1434x over previous
#include <cuda_runtime.h>
#include <cuda_bf16.h>
#include <math.h>
#include <stdint.h>

// Problem constants
#define Bb 2
#define Tt 4096
#define Cc 1024
#define NH 16
#define HS 64
#define BD 16
#define DELTA 32

#define TCHUNK 64
#define NROWS (TCHUNK + DELTA - 1)   // 95

#define MTOT (Bb * Tt)               // 8192
#define PW   (NH * 32)               // 512: width of P = x @ W_dsf

// Detect arch-specific ('a') compilation pass: tcgen05 only legal there.
#if defined(__CUDA_ARCH_FEAT_SM103_ALL) || \
    (defined(__CUDA_ARCH_SPECIFIC__) && defined(__CUDA_ARCH__) && (__CUDA_ARCH__ == 1030))
#define USE_TCGEN05 1
#else
#define USE_TCGEN05 0
#endif

// ---------------------------------------------------------------------------
// Scratch (__device__ globals; no allocations allowed)
// ---------------------------------------------------------------------------
__device__ float g_P   [MTOT * PW];              // projected disp (b*T+t, n*32+o)
__device__ float g_val [MTOT * Cc];
__device__ float g_attn[MTOT * Cc];
__device__ float g_pf  [DELTA * BD];

__device__ __nv_bfloat16 g_xhi[MTOT * Cc];
__device__ __nv_bfloat16 g_xlo[MTOT * Cc];
__device__ __nv_bfloat16 g_ahi[MTOT * Cc];
__device__ __nv_bfloat16 g_alo[MTOT * Cc];
__device__ __nv_bfloat16 g_wdh[PW * Cc];         // folded W_disp@W_sf, transposed split
__device__ __nv_bfloat16 g_wdl[PW * Cc];
__device__ __nv_bfloat16 g_wvh[Cc * Cc];
__device__ __nv_bfloat16 g_wvl[Cc * Cc];
__device__ __nv_bfloat16 g_wch[Cc * Cc];
__device__ __nv_bfloat16 g_wcl[Cc * Cc];

// ---------------------------------------------------------------------------
// Generic helpers
// ---------------------------------------------------------------------------
__device__ __forceinline__ uint32_t smem_u32(const void* p) {
    uint32_t a;
    asm("{ .reg .u64 t; cvta.to.shared.u64 t, %1; cvt.u32.u64 %0, t; }"
        : "=r"(a) : "l"(p));
    return a;
}

// --- HMMA fallback primitives (legal on plain sm_103) ---
__device__ __forceinline__ void cp_async16(uint32_t s, const void* g) {
    asm volatile("cp.async.cg.shared.global [%0], [%1], 16;" :: "r"(s), "l"(g) : "memory");
}
#define CP_COMMIT() asm volatile("cp.async.commit_group;" ::: "memory")
template <int N> __device__ __forceinline__ void cp_wait() {
    asm volatile("cp.async.wait_group %0;" :: "n"(N) : "memory");
}
__device__ __forceinline__ void ldsm_x4(uint32_t addr, uint32_t* r) {
    asm volatile("ldmatrix.sync.aligned.m8n8.x4.shared.b16 {%0,%1,%2,%3}, [%4];"
                 : "=r"(r[0]), "=r"(r[1]), "=r"(r[2]), "=r"(r[3]) : "r"(addr));
}
__device__ __forceinline__ void ldsm_x2(uint32_t addr, uint32_t* r) {
    asm volatile("ldmatrix.sync.aligned.m8n8.x2.shared.b16 {%0,%1}, [%2];"
                 : "=r"(r[0]), "=r"(r[1]) : "r"(addr));
}
__device__ __forceinline__ void mma16816(float* d, const uint32_t* a, const uint32_t* b) {
    asm volatile(
        "mma.sync.aligned.m16n8k16.row.col.f32.bf16.bf16.f32 "
        "{%0,%1,%2,%3}, {%4,%5,%6,%7}, {%8,%9}, {%0,%1,%2,%3};"
        : "+f"(d[0]), "+f"(d[1]), "+f"(d[2]), "+f"(d[3])
        : "r"(a[0]), "r"(a[1]), "r"(a[2]), "r"(a[3]), "r"(b[0]), "r"(b[1]));
}

#if USE_TCGEN05
__device__ __forceinline__ uint32_t elect_one() {
    uint32_t p;
    asm volatile("{\n\t.reg .pred p;\n\telect.sync _|p, 0xFFFFFFFF;\n\t"
                 "selp.b32 %0, 1, 0, p;\n\t}" : "=r"(p));
    return p;
}
#define MBAR_INIT(addr, cnt) \
    asm volatile("mbarrier.init.shared.b64 [%0], %1;" :: "r"(addr), "r"(cnt) : "memory")
#define MBAR_INVAL(addr) \
    asm volatile("mbarrier.inval.shared.b64 [%0];" :: "r"(addr) : "memory")
#define MBAR_WAIT_PARITY(mbar_addr, phase_parity) do {                         \
    uint32_t _mbar = (uint32_t)(mbar_addr);                                    \
    uint32_t _par  = (uint32_t)(phase_parity);                                 \
    uint32_t _done;                                                            \
    asm volatile("{\n\t.reg .pred p;\n\t"                                      \
        "mbarrier.try_wait.parity.acquire.cta.shared::cta.b64 p, [%1], %2;\n\t"\
        "selp.b32 %0, 1, 0, p;\n\t}"                                           \
        : "=r"(_done) : "r"(_mbar), "r"(_par) : "memory");                     \
    if (!_done) {                                                              \
        asm volatile("{\n\t.reg .pred P1;\n\t"                                 \
            "WAIT_LOOP_%=:\n\t"                                                \
            "mbarrier.try_wait.parity.acquire.cta.shared::cta.b64 P1, [%0], %1, 0x989680;\n\t" \
            "@P1 bra.uni WAIT_DONE_%=;\n\t"                                    \
            "bra.uni WAIT_LOOP_%=;\n\t"                                        \
            "WAIT_DONE_%=:\n\t}"                                               \
            :: "r"(_mbar), "r"(_par) : "memory");                              \
    }                                                                          \
} while (0)

#define TC_ALLOC(smem_res, ncols) \
    asm volatile("tcgen05.alloc.cta_group::1.sync.aligned.shared::cta.b32 [%0], %1;" \
                 :: "r"((uint32_t)(smem_res)), "r"((uint32_t)(ncols)) : "memory")
#define TC_DEALLOC(tmem, ncols) \
    asm volatile("tcgen05.dealloc.cta_group::1.sync.aligned.b32 %0, %1;" \
                 :: "r"(tmem), "r"((uint32_t)(ncols)))
#define TC_RELINQ() \
    asm volatile("tcgen05.relinquish_alloc_permit.cta_group::1.sync.aligned;")
#define TC_COMMIT(mbar) \
    asm volatile("tcgen05.commit.cta_group::1.mbarrier::arrive::one.shared::cluster.b64 [%0];" \
                 :: "r"((uint32_t)(mbar)) : "memory")
#define TC_FENCE_AFTER() \
    asm volatile("tcgen05.fence::after_thread_sync;" ::: "memory")
#define FENCE_ASYNC_SHARED() \
    asm volatile("fence.proxy.async.shared::cta;" ::: "memory")
#define TC_WAIT_LD() \
    asm volatile("tcgen05.wait::ld.sync.aligned;" ::: "memory")

#define TC_LD_X32(r, tmem_addr)                                                \
    asm volatile(                                                              \
        "tcgen05.ld.sync.aligned.32x32b.x32.b32 "                              \
        "{%0, %1, %2, %3, %4, %5, %6, %7, "                                    \
        " %8, %9, %10, %11, %12, %13, %14, %15, "                              \
        " %16, %17, %18, %19, %20, %21, %22, %23, "                            \
        " %24, %25, %26, %27, %28, %29, %30, %31}, [%32];"                     \
        : "=r"((r)[0]),  "=r"((r)[1]),  "=r"((r)[2]),  "=r"((r)[3]),           \
          "=r"((r)[4]),  "=r"((r)[5]),  "=r"((r)[6]),  "=r"((r)[7]),           \
          "=r"((r)[8]),  "=r"((r)[9]),  "=r"((r)[10]), "=r"((r)[11]),          \
          "=r"((r)[12]), "=r"((r)[13]), "=r"((r)[14]), "=r"((r)[15]),          \
          "=r"((r)[16]), "=r"((r)[17]), "=r"((r)[18]), "=r"((r)[19]),          \
          "=r"((r)[20]), "=r"((r)[21]), "=r"((r)[22]), "=r"((r)[23]),          \
          "=r"((r)[24]), "=r"((r)[25]), "=r"((r)[26]), "=r"((r)[27]),          \
          "=r"((r)[28]), "=r"((r)[29]), "=r"((r)[30]), "=r"((r)[31])           \
        : "r"(tmem_addr))

__device__ __forceinline__ void mma_bf16_ss(uint32_t d, uint64_t ad, uint64_t bd,
                                            uint32_t idesc, uint32_t en) {
    asm volatile("{\n\t.reg .pred p;\n\tsetp.ne.u32 p, %5, 0;\n\t"
                 "tcgen05.mma.cta_group::1.kind::f16 [%0], %1, %2, %3, "
                 "{%4, %4, %4, %4}, p;\n\t}"
                 :: "r"(d), "l"(ad), "l"(bd), "r"(idesc), "r"(0u), "r"(en)
                 : "memory");
}
static constexpr uint64_t DESC_BASE_SW128 =
    (uint64_t(2) << 61) | (uint64_t(1) << 46) | (uint64_t(64) << 32) | (uint64_t(1) << 16);
__device__ __forceinline__ uint64_t make_desc(uint32_t addr) {
    return DESC_BASE_SW128 | ((uint64_t)(addr >> 4) & 0x3FFF);
}
#define TG_IDESC 0x08200490u
#endif  // USE_TCGEN05

// ---------------------------------------------------------------------------
// Split fp32 -> (hi, lo) bf16
// ---------------------------------------------------------------------------
__global__ __launch_bounds__(256) void split4_kernel(const float* __restrict__ src,
                                                     __nv_bfloat16* __restrict__ hi,
                                                     __nv_bfloat16* __restrict__ lo,
                                                     int n) {
    int i = (blockIdx.x * 256 + threadIdx.x) * 4;
    if (i >= n) return;
    float4 v = *(const float4*)(src + i);
    __nv_bfloat16 h0 = __float2bfloat16(v.x);
    __nv_bfloat16 h1 = __float2bfloat16(v.y);
    __nv_bfloat16 h2 = __float2bfloat16(v.z);
    __nv_bfloat16 h3 = __float2bfloat16(v.w);
    __nv_bfloat16 l0 = __float2bfloat16(v.x - __bfloat162float(h0));
    __nv_bfloat16 l1 = __float2bfloat16(v.y - __bfloat162float(h1));
    __nv_bfloat16 l2 = __float2bfloat16(v.z - __bfloat162float(h2));
    __nv_bfloat16 l3 = __float2bfloat16(v.w - __bfloat162float(h3));
    __nv_bfloat162 hh0; hh0.x = h0; hh0.y = h1;
    __nv_bfloat162 hh1; hh1.x = h2; hh1.y = h3;
    __nv_bfloat162 ll0; ll0.x = l0; ll0.y = l1;
    __nv_bfloat162 ll1; ll1.x = l2; ll1.y = l3;
    *(__nv_bfloat162*)(hi + i)     = hh0;
    *(__nv_bfloat162*)(hi + i + 2) = hh1;
    *(__nv_bfloat162*)(lo + i)     = ll0;
    *(__nv_bfloat162*)(lo + i + 2) = ll1;
}

// ---------------------------------------------------------------------------
// Transpose + split: W (K,N) fp32 -> Wt hi/lo (N,K) bf16
// ---------------------------------------------------------------------------
__global__ __launch_bounds__(256) void tsplit_kernel(const float* __restrict__ W,
                                                     __nv_bfloat16* __restrict__ Th,
                                                     __nv_bfloat16* __restrict__ Tl,
                                                     int K, int N) {
    __shared__ float tile[32][33];
    int n0 = blockIdx.x * 32, k0 = blockIdx.y * 32;
    int tx = threadIdx.x, ty0 = threadIdx.y;
    for (int ty = ty0; ty < 32; ty += 8)
        tile[ty][tx] = W[(size_t)(k0 + ty) * N + n0 + tx];
    __syncthreads();
    for (int ty = ty0; ty < 32; ty += 8) {
        float v = tile[tx][ty];
        __nv_bfloat16 h = __float2bfloat16(v);
        __nv_bfloat16 l = __float2bfloat16(v - __bfloat162float(h));
        size_t o = (size_t)(n0 + ty) * K + k0 + tx;
        Th[o] = h;
        Tl[o] = l;
    }
}

// ---------------------------------------------------------------------------
// Fold W_disp (C, NH*16) and W_sf (16, 32) into W_dsf^T split bf16:
// out[(n*32+o), k] = sum_d W_disp[k, n*16+d] * W_sf[d, o]   (fp32 exact)
// ---------------------------------------------------------------------------
__global__ __launch_bounds__(256) void fold_kernel(const float* __restrict__ Wd,
                                                   const float* __restrict__ Wsf,
                                                   __nv_bfloat16* __restrict__ Th,
                                                   __nv_bfloat16* __restrict__ Tl) {
    int idx = blockIdx.x * 256 + threadIdx.x;      // 0 .. 512*1024-1
    int k  = idx & (Cc - 1);
    int no = idx >> 10;                            // 0..511
    int n = no >> 5, o = no & 31;
    float acc = 0.f;
#pragma unroll
    for (int d = 0; d < 16; d++)
        acc += Wd[(size_t)k * (NH * BD) + n * 16 + d] * Wsf[d * 32 + o];
    __nv_bfloat16 h = __float2bfloat16(acc);
    __nv_bfloat16 l = __float2bfloat16(acc - __bfloat162float(h));
    Th[(size_t)no * Cc + k] = h;
    Tl[(size_t)no * Cc + k] = l;
}

// ---------------------------------------------------------------------------
// Tensor-core split-GEMM: C(M,N) = (Ahi+Alo)(Bhi+Blo)^T, HH+HL+LH terms.
// ---------------------------------------------------------------------------
#define TG_SMEM_BYTES 148480

__global__ __launch_bounds__(256) void tgemm_kernel(const __nv_bfloat16* __restrict__ Ahi,
                                                    const __nv_bfloat16* __restrict__ Alo,
                                                    const __nv_bfloat16* __restrict__ Bhi,
                                                    const __nv_bfloat16* __restrict__ Blo,
                                                    float* __restrict__ C,
                                                    int M, int N, int K) {
    extern __shared__ char dsm[];
    int tid = threadIdx.x;
    int rowC = blockIdx.y * 128;
    int colC = blockIdx.x * 128;

#if USE_TCGEN05
    uint32_t smb = smem_u32(dsm);
    const uint32_t mbar = smb + 8;
    int wid = tid >> 5;

    if (wid == 0) TC_ALLOC(smb + 0, 128);
    if (tid == 0) MBAR_INIT(mbar, 1);
    __syncthreads();
    uint32_t tmem;
    asm volatile("ld.shared.b32 %0, [%1];" : "=r"(tmem) : "r"(smb + 0));

    const int NCHUNK = K >> 6;

    for (int c = 0; c < NCHUNK; c++) {
        if (c >= 2) MBAR_WAIT_PARITY(mbar, (c & 1));

        const int kbase = c << 6;
        char* buf = dsm + 1024 + (c & 1) * 65536;
        {
            const __nv_bfloat16* srcs[4] = { Ahi, Alo, Bhi, Blo };
            const int bases[4] = { rowC, rowC, colC, colC };
#pragma unroll
            for (int tno = 0; tno < 4; tno++) {
                const __nv_bfloat16* s = srcs[tno];
                const int r0 = bases[tno];
                char* tb = buf + tno * 16384;
#pragma unroll
                for (int it = 0; it < 4; it++) {
                    int idx = tid + it * 256;
                    int r = idx >> 3, cc = idx & 7;
                    uint4 v = *(const uint4*)(s + (size_t)(r0 + r) * K + kbase + cc * 8);
                    uint32_t off = r * 128 + cc * 16;
                    off ^= (off >> 3) & 0x70;
                    *(uint4*)(tb + off) = v;
                }
            }
        }
        FENCE_ASYNC_SHARED();
        __syncthreads();

        if (wid == 0 && elect_one()) {
            uint32_t b0 = smb + 1024 + (c & 1) * 65536;
            uint64_t dAh = make_desc(b0);
            uint64_t dAl = make_desc(b0 + 16384);
            uint64_t dBh = make_desc(b0 + 32768);
            uint64_t dBl = make_desc(b0 + 49152);
#pragma unroll
            for (int ks = 0; ks < 4; ks++)
                mma_bf16_ss(tmem, dAh + ks * 2, dBh + ks * 2, TG_IDESC,
                            (c == 0 && ks == 0) ? 0u : 1u);
#pragma unroll
            for (int ks = 0; ks < 4; ks++)
                mma_bf16_ss(tmem, dAh + ks * 2, dBl + ks * 2, TG_IDESC, 1u);
#pragma unroll
            for (int ks = 0; ks < 4; ks++)
                mma_bf16_ss(tmem, dAl + ks * 2, dBh + ks * 2, TG_IDESC, 1u);
            TC_COMMIT(mbar);
        }
    }

    MBAR_WAIT_PARITY(mbar, ((NCHUNK - 2) & 1));
    MBAR_WAIT_PARITY(mbar, ((NCHUNK - 1) & 1));
    TC_FENCE_AFTER();

    float* stage = (float*)(dsm + 1024);
#pragma unroll 1
    for (int g = 0; g < 4; g++) {
        if (tid < 128) {
            uint32_t dr[32];
            TC_LD_X32(dr, tmem + g * 32);
            TC_WAIT_LD();
            float* st = stage + tid * 36;
#pragma unroll
            for (int cc = 0; cc < 32; cc++) st[cc] = __uint_as_float(dr[cc]);
        }
        __syncthreads();
#pragma unroll
        for (int it = 0; it < 4; it++) {
            int idx = tid + it * 256;
            int r = idx >> 3, c4 = idx & 7;
            float4 v = *(float4*)(stage + r * 36 + c4 * 4);
            *(float4*)(C + (size_t)(rowC + r) * N + colC + g * 32 + c4 * 4) = v;
        }
        __syncthreads();
    }

    if (tid == 0) MBAR_INVAL(mbar);
    __syncthreads();
    if (wid == 0) {
        TC_RELINQ();
        TC_DEALLOC(tmem, 128);
    }

#else  // ------------------- HMMA mma.sync fallback -------------------------
    const int KC = 64;
    const int TILE_B = 128 * 144;
    uint32_t sbase = smem_u32(dsm) + 1024;
    int lane = tid & 31;
    int wid  = tid >> 5;
    int wm = wid & 1;
    int wn = wid >> 1;

    float acc[4][4][4];
#pragma unroll
    for (int mb = 0; mb < 4; mb++)
#pragma unroll
        for (int nb = 0; nb < 4; nb++)
#pragma unroll
            for (int q = 0; q < 4; q++) acc[mb][nb][q] = 0.f;

    const __nv_bfloat16* srcs[4] = { Ahi, Alo, Bhi, Blo };
    const int bases[4] = { rowC, rowC, colC, colC };

    const int NC = K / KC;

    {
        int kb = 0;
#pragma unroll
        for (int it = 0; it < 16; it++) {
            int idx = tid + it * 256;
            int tno = idx >> 10;
            int rem = idx & 1023;
            int r = rem >> 3, s = rem & 7;
            uint32_t sa = sbase + tno * TILE_B + r * 144 + s * 16;
            cp_async16(sa, srcs[tno] + (size_t)(bases[tno] + r) * K + kb + s * 8);
        }
        CP_COMMIT();
    }

#pragma unroll 1
    for (int c = 0; c < NC; c++) {
        if (c + 1 < NC) {
            int buf = (c + 1) & 1;
            int kb = (c + 1) * KC;
#pragma unroll
            for (int it = 0; it < 16; it++) {
                int idx = tid + it * 256;
                int tno = idx >> 10;
                int rem = idx & 1023;
                int r = rem >> 3, s = rem & 7;
                uint32_t sa = sbase + (buf * 4 + tno) * TILE_B + r * 144 + s * 16;
                cp_async16(sa, srcs[tno] + (size_t)(bases[tno] + r) * K + kb + s * 8);
            }
            CP_COMMIT();
            cp_wait<1>();
        } else {
            cp_wait<0>();
        }
        __syncthreads();

        uint32_t ah = sbase + (c & 1) * 4 * TILE_B;
        uint32_t al = ah + TILE_B;
        uint32_t bh = ah + 2 * TILE_B;
        uint32_t bl = ah + 3 * TILE_B;

#pragma unroll
        for (int kk = 0; kk < 4; kk++) {
            uint32_t afh[4][4], afl[4][4], bfh[4][2], bfl[4][2];
#pragma unroll
            for (int mb = 0; mb < 4; mb++) {
                uint32_t off = (uint32_t)(wm * 64 + mb * 16 + (lane & 15)) * 144
                             + (uint32_t)(lane >> 4) * 16 + kk * 32;
                ldsm_x4(ah + off, afh[mb]);
                ldsm_x4(al + off, afl[mb]);
            }
#pragma unroll
            for (int nb = 0; nb < 4; nb++) {
                uint32_t off = (uint32_t)(wn * 32 + nb * 8 + (lane & 7)) * 144
                             + (uint32_t)((lane >> 3) & 1) * 16 + kk * 32;
                ldsm_x2(bh + off, bfh[nb]);
                ldsm_x2(bl + off, bfl[nb]);
            }
#pragma unroll
            for (int mb = 0; mb < 4; mb++)
#pragma unroll
                for (int nb = 0; nb < 4; nb++) {
                    mma16816(acc[mb][nb], afh[mb], bfh[nb]);
                    mma16816(acc[mb][nb], afh[mb], bfl[nb]);
                    mma16816(acc[mb][nb], afl[mb], bfh[nb]);
                }
        }
        __syncthreads();
    }

#pragma unroll
    for (int mb = 0; mb < 4; mb++)
#pragma unroll
        for (int nb = 0; nb < 4; nb++) {
            int r0 = rowC + wm * 64 + mb * 16 + (lane >> 2);
            int c0 = colC + wn * 32 + nb * 8 + (lane & 3) * 2;
            *(float2*)(C + (size_t)r0 * N + c0) =
                make_float2(acc[mb][nb][0], acc[mb][nb][1]);
            *(float2*)(C + (size_t)(r0 + 8) * N + c0) =
                make_float2(acc[mb][nb][2], acc[mb][nb][3]);
        }
#endif
}

// ---------------------------------------------------------------------------
// pos_feat = rel_pos_emb(32x16) @ W_pos(16x16)
// ---------------------------------------------------------------------------
__global__ void posfeat_kernel(const float* __restrict__ rel,
                               const float* __restrict__ Wp) {
    int t = threadIdx.x;
    int r = t >> 4, c = t & 15;
    float acc = 0.f;
#pragma unroll
    for (int k = 0; k < 16; k++) acc += rel[r * 16 + k] * Wp[k * 16 + c];
    g_pf[r * 16 + c] = acc;
}

__device__ __forceinline__ float gelu_exact(float v) {
    return 0.5f * v * (1.0f + erff(v * 0.70710678118654752f));
}

// ---------------------------------------------------------------------------
// Windowed attention over precomputed P = x @ W_dsf.
// fused[t,j,o] = P[g,o] - P[t,o] + b_sf[o],  g = t + j - 31.
// One block = (b, head n, 64 t's). 256 threads, warp handles 8 t's, lane = j.
// ---------------------------------------------------------------------------
__global__ __launch_bounds__(256) void attn_kernel(const float* __restrict__ b_sf,
                                                   const float* __restrict__ w_bond,
                                                   const float* __restrict__ w_dmg,
                                                   const float* __restrict__ pb_dmg) {
    __shared__ float sm_val[NROWS * 64];
    __shared__ float sm_P  [NROWS * 33];        // 32 cols + pad
    __shared__ float sm_pf [32 * 17];
    __shared__ float sm_bsf[32];
    __shared__ float sm_wb[16], sm_wd[16];

    int tid  = threadIdx.x;
    int t0   = blockIdx.x * TCHUNK;
    int n    = blockIdx.y;
    int b    = blockIdx.z;

    const float* valp = g_val + (size_t)b * Tt * Cc;
    const float* Pp   = g_P   + (size_t)b * Tt * PW;
    float* outp       = g_attn + (size_t)b * Tt * Cc;

    for (int idx = tid; idx < NROWS * 64; idx += 256) {
        int r = idx >> 6, h = idx & 63;
        int g = t0 - (DELTA - 1) + r;
        sm_val[r * 64 + h] = (g >= 0) ? valp[(size_t)g * Cc + n * HS + h] : 0.f;
    }
    for (int idx = tid; idx < NROWS * 32; idx += 256) {
        int r = idx >> 5, o = idx & 31;
        int g = t0 - (DELTA - 1) + r;
        sm_P[r * 33 + o] = (g >= 0) ? Pp[(size_t)g * PW + n * 32 + o] : 0.f;
    }
    for (int idx = tid; idx < 512; idx += 256) {
        int r = idx >> 4, c = idx & 15;
        sm_pf[r * 17 + c] = g_pf[idx];
    }
    if (tid < 32) sm_bsf[tid] = b_sf[tid];
    if (tid < 16) { sm_wb[tid] = w_bond[tid]; sm_wd[tid] = w_dmg[tid]; }
    __syncthreads();

    const float bdmg = pb_dmg[0];
    int warp = tid >> 5;
    int lane = tid & 31;

#pragma unroll 1
    for (int i = 0; i < 8; i++) {
        int tl = warp * 8 + i;
        int t  = t0 + tl;

        const float* Pg = &sm_P[(tl + lane) * 33];
        const float* Ps = &sm_P[(tl + DELTA - 1) * 33];
        const float* pfr = &sm_pf[lane * 17];

        float bond = 0.f, dacc = 0.f;
#pragma unroll
        for (int o = 0; o < 16; o++) {
            float fb = Pg[o] - Ps[o] + sm_bsf[o];
            bond += gelu_exact(fb + pfr[o]) * sm_wb[o];
            float fd = Pg[o + 16] - Ps[o + 16] + sm_bsf[o + 16];
            dacc += gelu_exact(fd) * sm_wd[o];
        }
        float dmg   = 1.f / (1.f + __expf(-(dacc + bdmg)));
        float score = bond - 10.f * dmg;
        if (t + lane < DELTA - 1) score = -1e30f;

        float m = score;
#pragma unroll
        for (int off = 16; off > 0; off >>= 1)
            m = fmaxf(m, __shfl_xor_sync(0xFFFFFFFFu, m, off));
        float e = __expf(score - m);
        float ssum = e;
#pragma unroll
        for (int off = 16; off > 0; off >>= 1)
            ssum += __shfl_xor_sync(0xFFFFFFFFu, ssum, off);
        float w = e / ssum;

        float acc0 = 0.f, acc1 = 0.f;
#pragma unroll
        for (int j2 = 0; j2 < 32; j2++) {
            float wj = __shfl_sync(0xFFFFFFFFu, w, j2);
            const float* vrow = &sm_val[(tl + j2) * 64];
            acc0 += wj * vrow[lane];
            acc1 += wj * vrow[lane + 32];
        }
        float* orow = outp + (size_t)t * Cc + n * HS;
        orow[lane]      = acc0;
        orow[lane + 32] = acc1;
    }
}

// ---------------------------------------------------------------------------
extern "C" void kernel_launch(void* const* d_in, const int* in_sizes, int n_in,
                              void* d_out, int out_size) {
    const float* x       = (const float*)d_in[0];
    const float* W_disp  = (const float*)d_in[1];
    const float* W_val   = (const float*)d_in[2];
    const float* rel_pos = (const float*)d_in[3];
    const float* W_pos   = (const float*)d_in[4];
    const float* W_sf    = (const float*)d_in[5];
    const float* b_sf    = (const float*)d_in[6];
    const float* w_bond  = (const float*)d_in[7];
    const float* w_dmg   = (const float*)d_in[8];
    const float* b_dmg   = (const float*)d_in[9];
    const float* W_cproj = (const float*)d_in[10];
    float* out = (float*)d_out;

    float *P_p, *val_p, *attn_p;
    __nv_bfloat16 *xhi, *xlo, *ahi, *alo, *wdh, *wdl, *wvh, *wvl, *wch, *wcl;
    cudaGetSymbolAddress((void**)&P_p,   g_P);
    cudaGetSymbolAddress((void**)&val_p, g_val);
    cudaGetSymbolAddress((void**)&attn_p, g_attn);
    cudaGetSymbolAddress((void**)&xhi, g_xhi);
    cudaGetSymbolAddress((void**)&xlo, g_xlo);
    cudaGetSymbolAddress((void**)&ahi, g_ahi);
    cudaGetSymbolAddress((void**)&alo, g_alo);
    cudaGetSymbolAddress((void**)&wdh, g_wdh);
    cudaGetSymbolAddress((void**)&wdl, g_wdl);
    cudaGetSymbolAddress((void**)&wvh, g_wvh);
    cudaGetSymbolAddress((void**)&wvl, g_wvl);
    cudaGetSymbolAddress((void**)&wch, g_wch);
    cudaGetSymbolAddress((void**)&wcl, g_wcl);

    cudaFuncSetAttribute(tgemm_kernel,
                         cudaFuncAttributeMaxDynamicSharedMemorySize, TG_SMEM_BYTES);

    const int M = MTOT;
    const int NELEM = M * Cc;

    split4_kernel<<<NELEM / 1024, 256>>>(x, xhi, xlo, NELEM);
    fold_kernel<<<(PW * Cc) / 256, 256>>>(W_disp, W_sf, wdh, wdl);
    tsplit_kernel<<<dim3(Cc / 32, Cc / 32), dim3(32, 8)>>>(W_val,  wvh, wvl, Cc, Cc);
    tsplit_kernel<<<dim3(Cc / 32, Cc / 32), dim3(32, 8)>>>(W_cproj, wch, wcl, Cc, Cc);

    // P = x @ W_dsf   (M x 512)
    tgemm_kernel<<<dim3(PW / 128, M / 128), 256, TG_SMEM_BYTES>>>(
        xhi, xlo, wdh, wdl, P_p, M, PW, Cc);
    // val = x @ W_val (M x 1024)
    tgemm_kernel<<<dim3(Cc / 128, M / 128), 256, TG_SMEM_BYTES>>>(
        xhi, xlo, wvh, wvl, val_p, M, Cc, Cc);

    posfeat_kernel<<<1, 512>>>(rel_pos, W_pos);
    attn_kernel<<<dim3(Tt / TCHUNK, NH, Bb), 256>>>(b_sf, w_bond, w_dmg, b_dmg);

    split4_kernel<<<NELEM / 1024, 256>>>(attn_p, ahi, alo, NELEM);
    tgemm_kernel<<<dim3(Cc / 128, M / 128), 256, TG_SMEM_BYTES>>>(
        ahi, alo, wch, wcl, out, M, Cc, Cc);
}

// round 9
// speedup vs baseline: 2.7583x; 1.1367x over previous
#include <cuda_runtime.h>
#include <cuda_bf16.h>
#include <math.h>
#include <stdint.h>

// Problem constants
#define Bb 2
#define Tt 4096
#define Cc 1024
#define NH 16
#define HS 64
#define BD 16
#define DELTA 32

#define TCHUNK 64
#define NROWS (TCHUNK + DELTA - 1)   // 95

#define MTOT (Bb * Tt)               // 8192
#define PW   (NH * 32)               // 512: width of P = x @ W_dsf

// Detect arch-specific ('a') compilation pass: tcgen05 only legal there.
#if defined(__CUDA_ARCH_FEAT_SM103_ALL) || \
    (defined(__CUDA_ARCH_SPECIFIC__) && defined(__CUDA_ARCH__) && (__CUDA_ARCH__ == 1030))
#define USE_TCGEN05 1
#else
#define USE_TCGEN05 0
#endif

// ---------------------------------------------------------------------------
// Scratch (__device__ globals; no allocations allowed)
// ---------------------------------------------------------------------------
__device__ float g_P   [MTOT * PW];              // projected disp (b*T+t, n*32+o)
__device__ float g_val [MTOT * Cc];
__device__ float g_pf  [DELTA * BD];

__device__ __nv_bfloat16 g_xhi[MTOT * Cc];
__device__ __nv_bfloat16 g_xlo[MTOT * Cc];
__device__ __nv_bfloat16 g_ahi[MTOT * Cc];       // attn output, split bf16
__device__ __nv_bfloat16 g_alo[MTOT * Cc];
__device__ __nv_bfloat16 g_wdh[PW * Cc];         // folded W_disp@W_sf, transposed split
__device__ __nv_bfloat16 g_wdl[PW * Cc];
__device__ __nv_bfloat16 g_wvh[Cc * Cc];
__device__ __nv_bfloat16 g_wvl[Cc * Cc];
__device__ __nv_bfloat16 g_wch[Cc * Cc];
__device__ __nv_bfloat16 g_wcl[Cc * Cc];

// ---------------------------------------------------------------------------
// Generic helpers
// ---------------------------------------------------------------------------
__device__ __forceinline__ uint32_t smem_u32(const void* p) {
    uint32_t a;
    asm("{ .reg .u64 t; cvta.to.shared.u64 t, %1; cvt.u32.u64 %0, t; }"
        : "=r"(a) : "l"(p));
    return a;
}

// --- HMMA fallback primitives (legal on plain sm_103) ---
__device__ __forceinline__ void cp_async16(uint32_t s, const void* g) {
    asm volatile("cp.async.cg.shared.global [%0], [%1], 16;" :: "r"(s), "l"(g) : "memory");
}
#define CP_COMMIT() asm volatile("cp.async.commit_group;" ::: "memory")
template <int N> __device__ __forceinline__ void cp_wait() {
    asm volatile("cp.async.wait_group %0;" :: "n"(N) : "memory");
}
__device__ __forceinline__ void ldsm_x4(uint32_t addr, uint32_t* r) {
    asm volatile("ldmatrix.sync.aligned.m8n8.x4.shared.b16 {%0,%1,%2,%3}, [%4];"
                 : "=r"(r[0]), "=r"(r[1]), "=r"(r[2]), "=r"(r[3]) : "r"(addr));
}
__device__ __forceinline__ void ldsm_x2(uint32_t addr, uint32_t* r) {
    asm volatile("ldmatrix.sync.aligned.m8n8.x2.shared.b16 {%0,%1}, [%2];"
                 : "=r"(r[0]), "=r"(r[1]) : "r"(addr));
}
__device__ __forceinline__ void mma16816(float* d, const uint32_t* a, const uint32_t* b) {
    asm volatile(
        "mma.sync.aligned.m16n8k16.row.col.f32.bf16.bf16.f32 "
        "{%0,%1,%2,%3}, {%4,%5,%6,%7}, {%8,%9}, {%0,%1,%2,%3};"
        : "+f"(d[0]), "+f"(d[1]), "+f"(d[2]), "+f"(d[3])
        : "r"(a[0]), "r"(a[1]), "r"(a[2]), "r"(a[3]), "r"(b[0]), "r"(b[1]));
}

#if USE_TCGEN05
__device__ __forceinline__ uint32_t elect_one() {
    uint32_t p;
    asm volatile("{\n\t.reg .pred p;\n\telect.sync _|p, 0xFFFFFFFF;\n\t"
                 "selp.b32 %0, 1, 0, p;\n\t}" : "=r"(p));
    return p;
}
#define MBAR_INIT(addr, cnt) \
    asm volatile("mbarrier.init.shared.b64 [%0], %1;" :: "r"(addr), "r"(cnt) : "memory")
#define MBAR_INVAL(addr) \
    asm volatile("mbarrier.inval.shared.b64 [%0];" :: "r"(addr) : "memory")
#define MBAR_WAIT_PARITY(mbar_addr, phase_parity) do {                         \
    uint32_t _mbar = (uint32_t)(mbar_addr);                                    \
    uint32_t _par  = (uint32_t)(phase_parity);                                 \
    uint32_t _done;                                                            \
    asm volatile("{\n\t.reg .pred p;\n\t"                                      \
        "mbarrier.try_wait.parity.acquire.cta.shared::cta.b64 p, [%1], %2;\n\t"\
        "selp.b32 %0, 1, 0, p;\n\t}"                                           \
        : "=r"(_done) : "r"(_mbar), "r"(_par) : "memory");                     \
    if (!_done) {                                                              \
        asm volatile("{\n\t.reg .pred P1;\n\t"                                 \
            "WAIT_LOOP_%=:\n\t"                                                \
            "mbarrier.try_wait.parity.acquire.cta.shared::cta.b64 P1, [%0], %1, 0x989680;\n\t" \
            "@P1 bra.uni WAIT_DONE_%=;\n\t"                                    \
            "bra.uni WAIT_LOOP_%=;\n\t"                                        \
            "WAIT_DONE_%=:\n\t}"                                               \
            :: "r"(_mbar), "r"(_par) : "memory");                              \
    }                                                                          \
} while (0)

#define TC_ALLOC(smem_res, ncols) \
    asm volatile("tcgen05.alloc.cta_group::1.sync.aligned.shared::cta.b32 [%0], %1;" \
                 :: "r"((uint32_t)(smem_res)), "r"((uint32_t)(ncols)) : "memory")
#define TC_DEALLOC(tmem, ncols) \
    asm volatile("tcgen05.dealloc.cta_group::1.sync.aligned.b32 %0, %1;" \
                 :: "r"(tmem), "r"((uint32_t)(ncols)))
#define TC_RELINQ() \
    asm volatile("tcgen05.relinquish_alloc_permit.cta_group::1.sync.aligned;")
#define TC_COMMIT(mbar) \
    asm volatile("tcgen05.commit.cta_group::1.mbarrier::arrive::one.shared::cluster.b64 [%0];" \
                 :: "r"((uint32_t)(mbar)) : "memory")
#define TC_FENCE_AFTER() \
    asm volatile("tcgen05.fence::after_thread_sync;" ::: "memory")
#define FENCE_ASYNC_SHARED() \
    asm volatile("fence.proxy.async.shared::cta;" ::: "memory")
#define TC_WAIT_LD() \
    asm volatile("tcgen05.wait::ld.sync.aligned;" ::: "memory")

#define TC_LD_X32(r, tmem_addr)                                                \
    asm volatile(                                                              \
        "tcgen05.ld.sync.aligned.32x32b.x32.b32 "                              \
        "{%0, %1, %2, %3, %4, %5, %6, %7, "                                    \
        " %8, %9, %10, %11, %12, %13, %14, %15, "                              \
        " %16, %17, %18, %19, %20, %21, %22, %23, "                            \
        " %24, %25, %26, %27, %28, %29, %30, %31}, [%32];"                     \
        : "=r"((r)[0]),  "=r"((r)[1]),  "=r"((r)[2]),  "=r"((r)[3]),           \
          "=r"((r)[4]),  "=r"((r)[5]),  "=r"((r)[6]),  "=r"((r)[7]),           \
          "=r"((r)[8]),  "=r"((r)[9]),  "=r"((r)[10]), "=r"((r)[11]),          \
          "=r"((r)[12]), "=r"((r)[13]), "=r"((r)[14]), "=r"((r)[15]),          \
          "=r"((r)[16]), "=r"((r)[17]), "=r"((r)[18]), "=r"((r)[19]),          \
          "=r"((r)[20]), "=r"((r)[21]), "=r"((r)[22]), "=r"((r)[23]),          \
          "=r"((r)[24]), "=r"((r)[25]), "=r"((r)[26]), "=r"((r)[27]),          \
          "=r"((r)[28]), "=r"((r)[29]), "=r"((r)[30]), "=r"((r)[31])           \
        : "r"(tmem_addr))

__device__ __forceinline__ void mma_bf16_ss(uint32_t d, uint64_t ad, uint64_t bd,
                                            uint32_t idesc, uint32_t en) {
    asm volatile("{\n\t.reg .pred p;\n\tsetp.ne.u32 p, %5, 0;\n\t"
                 "tcgen05.mma.cta_group::1.kind::f16 [%0], %1, %2, %3, "
                 "{%4, %4, %4, %4}, p;\n\t}"
                 :: "r"(d), "l"(ad), "l"(bd), "r"(idesc), "r"(0u), "r"(en)
                 : "memory");
}
static constexpr uint64_t DESC_BASE_SW128 =
    (uint64_t(2) << 61) | (uint64_t(1) << 46) | (uint64_t(64) << 32) | (uint64_t(1) << 16);
__device__ __forceinline__ uint64_t make_desc(uint32_t addr) {
    return DESC_BASE_SW128 | ((uint64_t)(addr >> 4) & 0x3FFF);
}
#define TG_IDESC 0x08200490u
#endif  // USE_TCGEN05

// ---------------------------------------------------------------------------
// Split fp32 -> (hi, lo) bf16
// ---------------------------------------------------------------------------
__global__ __launch_bounds__(256) void split4_kernel(const float* __restrict__ src,
                                                     __nv_bfloat16* __restrict__ hi,
                                                     __nv_bfloat16* __restrict__ lo,
                                                     int n) {
    int i = (blockIdx.x * 256 + threadIdx.x) * 4;
    if (i >= n) return;
    float4 v = *(const float4*)(src + i);
    __nv_bfloat16 h0 = __float2bfloat16(v.x);
    __nv_bfloat16 h1 = __float2bfloat16(v.y);
    __nv_bfloat16 h2 = __float2bfloat16(v.z);
    __nv_bfloat16 h3 = __float2bfloat16(v.w);
    __nv_bfloat16 l0 = __float2bfloat16(v.x - __bfloat162float(h0));
    __nv_bfloat16 l1 = __float2bfloat16(v.y - __bfloat162float(h1));
    __nv_bfloat16 l2 = __float2bfloat16(v.z - __bfloat162float(h2));
    __nv_bfloat16 l3 = __float2bfloat16(v.w - __bfloat162float(h3));
    __nv_bfloat162 hh0; hh0.x = h0; hh0.y = h1;
    __nv_bfloat162 hh1; hh1.x = h2; hh1.y = h3;
    __nv_bfloat162 ll0; ll0.x = l0; ll0.y = l1;
    __nv_bfloat162 ll1; ll1.x = l2; ll1.y = l3;
    *(__nv_bfloat162*)(hi + i)     = hh0;
    *(__nv_bfloat162*)(hi + i + 2) = hh1;
    *(__nv_bfloat162*)(lo + i)     = ll0;
    *(__nv_bfloat162*)(lo + i + 2) = ll1;
}

// ---------------------------------------------------------------------------
// Transpose + split: W (K,N) fp32 -> Wt hi/lo (N,K) bf16
// ---------------------------------------------------------------------------
__global__ __launch_bounds__(256) void tsplit_kernel(const float* __restrict__ W,
                                                     __nv_bfloat16* __restrict__ Th,
                                                     __nv_bfloat16* __restrict__ Tl,
                                                     int K, int N) {
    __shared__ float tile[32][33];
    int n0 = blockIdx.x * 32, k0 = blockIdx.y * 32;
    int tx = threadIdx.x, ty0 = threadIdx.y;
    for (int ty = ty0; ty < 32; ty += 8)
        tile[ty][tx] = W[(size_t)(k0 + ty) * N + n0 + tx];
    __syncthreads();
    for (int ty = ty0; ty < 32; ty += 8) {
        float v = tile[tx][ty];
        __nv_bfloat16 h = __float2bfloat16(v);
        __nv_bfloat16 l = __float2bfloat16(v - __bfloat162float(h));
        size_t o = (size_t)(n0 + ty) * K + k0 + tx;
        Th[o] = h;
        Tl[o] = l;
    }
}

// ---------------------------------------------------------------------------
// Fold W_disp (C, NH*16) and W_sf (16, 32) into W_dsf^T split bf16:
// out[(n*32+o), k] = sum_d W_disp[k, n*16+d] * W_sf[d, o]   (fp32 exact)
// ---------------------------------------------------------------------------
__global__ __launch_bounds__(256) void fold_kernel(const float* __restrict__ Wd,
                                                   const float* __restrict__ Wsf,
                                                   __nv_bfloat16* __restrict__ Th,
                                                   __nv_bfloat16* __restrict__ Tl) {
    int idx = blockIdx.x * 256 + threadIdx.x;      // 0 .. 512*1024-1
    int k  = idx & (Cc - 1);
    int no = idx >> 10;                            // 0..511
    int n = no >> 5, o = no & 31;
    float acc = 0.f;
#pragma unroll
    for (int d = 0; d < 16; d++)
        acc += Wd[(size_t)k * (NH * BD) + n * 16 + d] * Wsf[d * 32 + o];
    __nv_bfloat16 h = __float2bfloat16(acc);
    __nv_bfloat16 l = __float2bfloat16(acc - __bfloat162float(h));
    Th[(size_t)no * Cc + k] = h;
    Tl[(size_t)no * Cc + k] = l;
}

// ---------------------------------------------------------------------------
// Tensor-core split-GEMM: C(M,N) = (Ahi+Alo)(Bhi+Blo)^T, HH+HL+LH terms.
// ---------------------------------------------------------------------------
#define TG_SMEM_BYTES 148480

__global__ __launch_bounds__(256) void tgemm_kernel(const __nv_bfloat16* __restrict__ Ahi,
                                                    const __nv_bfloat16* __restrict__ Alo,
                                                    const __nv_bfloat16* __restrict__ Bhi,
                                                    const __nv_bfloat16* __restrict__ Blo,
                                                    float* __restrict__ C,
                                                    int M, int N, int K) {
    extern __shared__ char dsm[];
    int tid = threadIdx.x;
    int rowC = blockIdx.y * 128;
    int colC = blockIdx.x * 128;

#if USE_TCGEN05
    uint32_t smb = smem_u32(dsm);
    const uint32_t mbar = smb + 8;
    int wid = tid >> 5;

    if (wid == 0) TC_ALLOC(smb + 0, 128);
    if (tid == 0) MBAR_INIT(mbar, 1);
    __syncthreads();
    uint32_t tmem;
    asm volatile("ld.shared.b32 %0, [%1];" : "=r"(tmem) : "r"(smb + 0));

    const int NCHUNK = K >> 6;

    for (int c = 0; c < NCHUNK; c++) {
        if (c >= 2) MBAR_WAIT_PARITY(mbar, (c & 1));

        const int kbase = c << 6;
        char* buf = dsm + 1024 + (c & 1) * 65536;
        {
            const __nv_bfloat16* srcs[4] = { Ahi, Alo, Bhi, Blo };
            const int bases[4] = { rowC, rowC, colC, colC };
#pragma unroll
            for (int tno = 0; tno < 4; tno++) {
                const __nv_bfloat16* s = srcs[tno];
                const int r0 = bases[tno];
                char* tb = buf + tno * 16384;
#pragma unroll
                for (int it = 0; it < 4; it++) {
                    int idx = tid + it * 256;
                    int r = idx >> 3, cc = idx & 7;
                    uint4 v = *(const uint4*)(s + (size_t)(r0 + r) * K + kbase + cc * 8);
                    uint32_t off = r * 128 + cc * 16;
                    off ^= (off >> 3) & 0x70;
                    *(uint4*)(tb + off) = v;
                }
            }
        }
        FENCE_ASYNC_SHARED();
        __syncthreads();

        if (wid == 0 && elect_one()) {
            uint32_t b0 = smb + 1024 + (c & 1) * 65536;
            uint64_t dAh = make_desc(b0);
            uint64_t dAl = make_desc(b0 + 16384);
            uint64_t dBh = make_desc(b0 + 32768);
            uint64_t dBl = make_desc(b0 + 49152);
#pragma unroll
            for (int ks = 0; ks < 4; ks++)
                mma_bf16_ss(tmem, dAh + ks * 2, dBh + ks * 2, TG_IDESC,
                            (c == 0 && ks == 0) ? 0u : 1u);
#pragma unroll
            for (int ks = 0; ks < 4; ks++)
                mma_bf16_ss(tmem, dAh + ks * 2, dBl + ks * 2, TG_IDESC, 1u);
#pragma unroll
            for (int ks = 0; ks < 4; ks++)
                mma_bf16_ss(tmem, dAl + ks * 2, dBh + ks * 2, TG_IDESC, 1u);
            TC_COMMIT(mbar);
        }
    }

    MBAR_WAIT_PARITY(mbar, ((NCHUNK - 2) & 1));
    MBAR_WAIT_PARITY(mbar, ((NCHUNK - 1) & 1));
    TC_FENCE_AFTER();

    float* stage = (float*)(dsm + 1024);
#pragma unroll 1
    for (int g = 0; g < 4; g++) {
        if (tid < 128) {
            uint32_t dr[32];
            TC_LD_X32(dr, tmem + g * 32);
            TC_WAIT_LD();
            float* st = stage + tid * 36;
#pragma unroll
            for (int cc = 0; cc < 32; cc++) st[cc] = __uint_as_float(dr[cc]);
        }
        __syncthreads();
#pragma unroll
        for (int it = 0; it < 4; it++) {
            int idx = tid + it * 256;
            int r = idx >> 3, c4 = idx & 7;
            float4 v = *(float4*)(stage + r * 36 + c4 * 4);
            *(float4*)(C + (size_t)(rowC + r) * N + colC + g * 32 + c4 * 4) = v;
        }
        __syncthreads();
    }

    if (tid == 0) MBAR_INVAL(mbar);
    __syncthreads();
    if (wid == 0) {
        TC_RELINQ();
        TC_DEALLOC(tmem, 128);
    }

#else  // ------------------- HMMA mma.sync fallback -------------------------
    const int KC = 64;
    const int TILE_B = 128 * 144;
    uint32_t sbase = smem_u32(dsm) + 1024;
    int lane = tid & 31;
    int wid  = tid >> 5;
    int wm = wid & 1;
    int wn = wid >> 1;

    float acc[4][4][4];
#pragma unroll
    for (int mb = 0; mb < 4; mb++)
#pragma unroll
        for (int nb = 0; nb < 4; nb++)
#pragma unroll
            for (int q = 0; q < 4; q++) acc[mb][nb][q] = 0.f;

    const __nv_bfloat16* srcs[4] = { Ahi, Alo, Bhi, Blo };
    const int bases[4] = { rowC, rowC, colC, colC };

    const int NC = K / KC;

    {
        int kb = 0;
#pragma unroll
        for (int it = 0; it < 16; it++) {
            int idx = tid + it * 256;
            int tno = idx >> 10;
            int rem = idx & 1023;
            int r = rem >> 3, s = rem & 7;
            uint32_t sa = sbase + tno * TILE_B + r * 144 + s * 16;
            cp_async16(sa, srcs[tno] + (size_t)(bases[tno] + r) * K + kb + s * 8);
        }
        CP_COMMIT();
    }

#pragma unroll 1
    for (int c = 0; c < NC; c++) {
        if (c + 1 < NC) {
            int buf = (c + 1) & 1;
            int kb = (c + 1) * KC;
#pragma unroll
            for (int it = 0; it < 16; it++) {
                int idx = tid + it * 256;
                int tno = idx >> 10;
                int rem = idx & 1023;
                int r = rem >> 3, s = rem & 7;
                uint32_t sa = sbase + (buf * 4 + tno) * TILE_B + r * 144 + s * 16;
                cp_async16(sa, srcs[tno] + (size_t)(bases[tno] + r) * K + kb + s * 8);
            }
            CP_COMMIT();
            cp_wait<1>();
        } else {
            cp_wait<0>();
        }
        __syncthreads();

        uint32_t ah = sbase + (c & 1) * 4 * TILE_B;
        uint32_t al = ah + TILE_B;
        uint32_t bh = ah + 2 * TILE_B;
        uint32_t bl = ah + 3 * TILE_B;

#pragma unroll
        for (int kk = 0; kk < 4; kk++) {
            uint32_t afh[4][4], afl[4][4], bfh[4][2], bfl[4][2];
#pragma unroll
            for (int mb = 0; mb < 4; mb++) {
                uint32_t off = (uint32_t)(wm * 64 + mb * 16 + (lane & 15)) * 144
                             + (uint32_t)(lane >> 4) * 16 + kk * 32;
                ldsm_x4(ah + off, afh[mb]);
                ldsm_x4(al + off, afl[mb]);
            }
#pragma unroll
            for (int nb = 0; nb < 4; nb++) {
                uint32_t off = (uint32_t)(wn * 32 + nb * 8 + (lane & 7)) * 144
                             + (uint32_t)((lane >> 3) & 1) * 16 + kk * 32;
                ldsm_x2(bh + off, bfh[nb]);
                ldsm_x2(bl + off, bfl[nb]);
            }
#pragma unroll
            for (int mb = 0; mb < 4; mb++)
#pragma unroll
                for (int nb = 0; nb < 4; nb++) {
                    mma16816(acc[mb][nb], afh[mb], bfh[nb]);
                    mma16816(acc[mb][nb], afh[mb], bfl[nb]);
                    mma16816(acc[mb][nb], afl[mb], bfh[nb]);
                }
        }
        __syncthreads();
    }

#pragma unroll
    for (int mb = 0; mb < 4; mb++)
#pragma unroll
        for (int nb = 0; nb < 4; nb++) {
            int r0 = rowC + wm * 64 + mb * 16 + (lane >> 2);
            int c0 = colC + wn * 32 + nb * 8 + (lane & 3) * 2;
            *(float2*)(C + (size_t)r0 * N + c0) =
                make_float2(acc[mb][nb][0], acc[mb][nb][1]);
            *(float2*)(C + (size_t)(r0 + 8) * N + c0) =
                make_float2(acc[mb][nb][2], acc[mb][nb][3]);
        }
#endif
}

// ---------------------------------------------------------------------------
// pos_feat = rel_pos_emb(32x16) @ W_pos(16x16)
// ---------------------------------------------------------------------------
__global__ void posfeat_kernel(const float* __restrict__ rel,
                               const float* __restrict__ Wp) {
    int t = threadIdx.x;
    int r = t >> 4, c = t & 15;
    float acc = 0.f;
#pragma unroll
    for (int k = 0; k < 16; k++) acc += rel[r * 16 + k] * Wp[k * 16 + c];
    g_pf[r * 16 + c] = acc;
}

// tanh-form gelu via HW tanh.approx (err analysis: final rel err ~1e-5)
__device__ __forceinline__ float gelu_t(float v) {
    float vv = v * v;
    float u  = fmaf(0.044715f * v, vv, v) * 0.7978845608028654f;
    float t;
    asm("tanh.approx.f32 %0, %1;" : "=f"(t) : "f"(u));
    float hv = 0.5f * v;
    return fmaf(hv, t, hv);
}

// ---------------------------------------------------------------------------
// Windowed attention over precomputed P = x @ W_dsf.
// fused[t,j,o] = P[g,o] - P[t,o] + b_sf[o],  g = t + j - 31.
// One block = (b, head n, 64 t's). 256 threads, warp handles 8 t's, lane = j.
// Writes split-bf16 output directly into g_ahi/g_alo.
// ---------------------------------------------------------------------------
__global__ __launch_bounds__(256) void attn_kernel(const float* __restrict__ b_sf,
                                                   const float* __restrict__ w_bond,
                                                   const float* __restrict__ w_dmg,
                                                   const float* __restrict__ pb_dmg) {
    __shared__ float sm_val[NROWS * 64];
    __shared__ float sm_P  [NROWS * 33];        // 32 cols + pad
    __shared__ float sm_pf [32 * 17];           // b_sf[:16] + pos_feat (bond half)
    __shared__ float sm_bsd[16];                // b_sf[16:32] (damage half)
    __shared__ float sm_wb[16], sm_wd[16];

    int tid  = threadIdx.x;
    int t0   = blockIdx.x * TCHUNK;
    int n    = blockIdx.y;
    int b    = blockIdx.z;

    const float* valp = g_val + (size_t)b * Tt * Cc;
    const float* Pp   = g_P   + (size_t)b * Tt * PW;

    for (int idx = tid; idx < NROWS * 64; idx += 256) {
        int r = idx >> 6, h = idx & 63;
        int g = t0 - (DELTA - 1) + r;
        sm_val[r * 64 + h] = (g >= 0) ? valp[(size_t)g * Cc + n * HS + h] : 0.f;
    }
    for (int idx = tid; idx < NROWS * 32; idx += 256) {
        int r = idx >> 5, o = idx & 31;
        int g = t0 - (DELTA - 1) + r;
        sm_P[r * 33 + o] = (g >= 0) ? Pp[(size_t)g * PW + n * 32 + o] : 0.f;
    }
    for (int idx = tid; idx < 512; idx += 256) {
        int r = idx >> 4, c = idx & 15;
        sm_pf[r * 17 + c] = g_pf[idx] + b_sf[c];    // fold bond bias in
    }
    if (tid < 16) {
        sm_bsd[tid] = b_sf[tid + 16];
        sm_wb[tid] = w_bond[tid];
        sm_wd[tid] = w_dmg[tid];
    }
    __syncthreads();

    const float bdmg = pb_dmg[0];
    int warp = tid >> 5;
    int lane = tid & 31;

#pragma unroll 1
    for (int i = 0; i < 8; i++) {
        int tl = warp * 8 + i;
        int t  = t0 + tl;

        const float* Pg  = &sm_P[(tl + lane) * 33];
        const float* Ps  = &sm_P[(tl + DELTA - 1) * 33];
        const float* pfr = &sm_pf[lane * 17];

        float bond = 0.f, dacc = 0.f;
#pragma unroll
        for (int o = 0; o < 16; o++) {
            float fb = Pg[o] - Ps[o] + pfr[o];
            bond = fmaf(gelu_t(fb), sm_wb[o], bond);
            float fd = Pg[o + 16] - Ps[o + 16] + sm_bsd[o];
            dacc = fmaf(gelu_t(fd), sm_wd[o], dacc);
        }
        float dmg   = 1.f / (1.f + __expf(-(dacc + bdmg)));
        float score = bond - 10.f * dmg;
        // masked lanes: exp(-30) ~ 9e-14 vs in-window exp >= 2.7e-5 -> weight < 4e-9
        if (t + lane < DELTA - 1) score = -30.f;

        // softmax without max-subtraction (scores bounded in (-10.5, 0.2))
        float e = __expf(score);
        float ssum = e;
#pragma unroll
        for (int off = 16; off > 0; off >>= 1)
            ssum += __shfl_xor_sync(0xFFFFFFFFu, ssum, off);
        float w = __fdividef(e, ssum);

        // out[h] = sum_j w_j * val[t+j-31][h]; lane covers h = 2*lane, 2*lane+1
        float acc0 = 0.f, acc1 = 0.f;
#pragma unroll
        for (int j2 = 0; j2 < 32; j2++) {
            float wj = __shfl_sync(0xFFFFFFFFu, w, j2);
            float2 vv = *(const float2*)&sm_val[(tl + j2) * 64 + 2 * lane];
            acc0 = fmaf(wj, vv.x, acc0);
            acc1 = fmaf(wj, vv.y, acc1);
        }

        // split to bf16 hi/lo and store coalesced
        size_t obase = ((size_t)(b * Tt + t)) * Cc + n * HS + 2 * lane;
        __nv_bfloat16 h0 = __float2bfloat16(acc0);
        __nv_bfloat16 h1 = __float2bfloat16(acc1);
        __nv_bfloat16 l0 = __float2bfloat16(acc0 - __bfloat162float(h0));
        __nv_bfloat16 l1 = __float2bfloat16(acc1 - __bfloat162float(h1));
        __nv_bfloat162 hh; hh.x = h0; hh.y = h1;
        __nv_bfloat162 ll; ll.x = l0; ll.y = l1;
        *(__nv_bfloat162*)&g_ahi[obase] = hh;
        *(__nv_bfloat162*)&g_alo[obase] = ll;
    }
}

// ---------------------------------------------------------------------------
extern "C" void kernel_launch(void* const* d_in, const int* in_sizes, int n_in,
                              void* d_out, int out_size) {
    const float* x       = (const float*)d_in[0];
    const float* W_disp  = (const float*)d_in[1];
    const float* W_val   = (const float*)d_in[2];
    const float* rel_pos = (const float*)d_in[3];
    const float* W_pos   = (const float*)d_in[4];
    const float* W_sf    = (const float*)d_in[5];
    const float* b_sf    = (const float*)d_in[6];
    const float* w_bond  = (const float*)d_in[7];
    const float* w_dmg   = (const float*)d_in[8];
    const float* b_dmg   = (const float*)d_in[9];
    const float* W_cproj = (const float*)d_in[10];
    float* out = (float*)d_out;

    float *P_p, *val_p;
    __nv_bfloat16 *xhi, *xlo, *ahi, *alo, *wdh, *wdl, *wvh, *wvl, *wch, *wcl;
    cudaGetSymbolAddress((void**)&P_p,   g_P);
    cudaGetSymbolAddress((void**)&val_p, g_val);
    cudaGetSymbolAddress((void**)&xhi, g_xhi);
    cudaGetSymbolAddress((void**)&xlo, g_xlo);
    cudaGetSymbolAddress((void**)&ahi, g_ahi);
    cudaGetSymbolAddress((void**)&alo, g_alo);
    cudaGetSymbolAddress((void**)&wdh, g_wdh);
    cudaGetSymbolAddress((void**)&wdl, g_wdl);
    cudaGetSymbolAddress((void**)&wvh, g_wvh);
    cudaGetSymbolAddress((void**)&wvl, g_wvl);
    cudaGetSymbolAddress((void**)&wch, g_wch);
    cudaGetSymbolAddress((void**)&wcl, g_wcl);

    cudaFuncSetAttribute(tgemm_kernel,
                         cudaFuncAttributeMaxDynamicSharedMemorySize, TG_SMEM_BYTES);

    const int M = MTOT;
    const int NELEM = M * Cc;

    split4_kernel<<<NELEM / 1024, 256>>>(x, xhi, xlo, NELEM);
    fold_kernel<<<(PW * Cc) / 256, 256>>>(W_disp, W_sf, wdh, wdl);
    tsplit_kernel<<<dim3(Cc / 32, Cc / 32), dim3(32, 8)>>>(W_val,  wvh, wvl, Cc, Cc);
    tsplit_kernel<<<dim3(Cc / 32, Cc / 32), dim3(32, 8)>>>(W_cproj, wch, wcl, Cc, Cc);

    // P = x @ W_dsf   (M x 512)
    tgemm_kernel<<<dim3(PW / 128, M / 128), 256, TG_SMEM_BYTES>>>(
        xhi, xlo, wdh, wdl, P_p, M, PW, Cc);
    // val = x @ W_val (M x 1024)
    tgemm_kernel<<<dim3(Cc / 128, M / 128), 256, TG_SMEM_BYTES>>>(
        xhi, xlo, wvh, wvl, val_p, M, Cc, Cc);

    posfeat_kernel<<<1, 512>>>(rel_pos, W_pos);
    attn_kernel<<<dim3(Tt / TCHUNK, NH, Bb), 256>>>(b_sf, w_bond, w_dmg, b_dmg);

    // out = attn @ W_cproj (attn already split by attn_kernel)
    tgemm_kernel<<<dim3(Cc / 128, M / 128), 256, TG_SMEM_BYTES>>>(
        ahi, alo, wch, wcl, out, M, Cc, Cc);
}